// round 2
// baseline (speedup 1.0000x reference)
#include <cuda_runtime.h>
#include <math.h>

#define TSTEPS 1024
#define BATCH  64
#define HID    512

// ---------------- scratch (static device allocations; no cudaMalloc) ----------------
__device__ float g_Zf[(size_t)TSTEPS * BATCH * 2048];   // 512 MB  Z fwd  [t][b][4H]
__device__ float g_Zb[(size_t)TSTEPS * BATCH * 2048];   // 512 MB  Z bwd  [t][b][4H]
__device__ float g_h1[(size_t)BATCH * TSTEPS * 1024];   // 256 MB  layer1 out [b][t][2H]
__device__ float g_h2[(size_t)BATCH * TSTEPS * 1024];   // 256 MB  layer2 out [b][t][2H]
__device__ float g_hst[2][2][HID][BATCH];               // h state [dir][phase][col][b]
__device__ unsigned int g_bar;

// =====================================================================
//  SGEMM: C[M=65536, N] = A[M,K] @ B[K,N] (+bias)
//  MODE 0: out layout [t][b][N]  (row r -> b=r>>10, t=r&1023)   (Z buffers)
//  MODE 1: out row-major [r][N], A := A + A2 elementwise         (final dense)
// =====================================================================
template <int MODE>
__global__ void __launch_bounds__(256, 2)
sgemm_kernel(const float* __restrict__ A, const float* __restrict__ A2,
             const float* __restrict__ Bw, const float* __restrict__ bias,
             float* __restrict__ C, int K, int N)
{
    __shared__ float As[8][128];
    __shared__ float Bs[8][128];

    const int tid = threadIdx.x;
    const int rowBase = blockIdx.y * 128;
    const int colBase = blockIdx.x * 128;
    const int tx = tid & 15;      // 16 col groups
    const int ty = tid >> 4;      // 16 row groups

    // loader mapping
    const int arow = tid >> 1;
    const int akq  = (tid & 1) * 4;
    const int brow = tid >> 5;
    const int bcol = (tid & 31) * 4;

    const float* Ap  = A + (size_t)(rowBase + arow) * K + akq;
    const float* A2p = (MODE == 1) ? (A2 + (size_t)(rowBase + arow) * K + akq) : Ap;
    const float* Bp  = Bw + (size_t)brow * N + colBase + bcol;

    // prefetch tile 0
    float4 aReg = *(const float4*)Ap;
    if (MODE == 1) {
        float4 t = *(const float4*)A2p;
        aReg.x += t.x; aReg.y += t.y; aReg.z += t.z; aReg.w += t.w;
    }
    float4 bReg = *(const float4*)Bp;

    float acc[8][8];
#pragma unroll
    for (int i = 0; i < 8; ++i)
#pragma unroll
        for (int j = 0; j < 8; ++j) acc[i][j] = 0.f;

    for (int kt = 0; kt < K; kt += 8) {
        As[akq + 0][arow] = aReg.x;
        As[akq + 1][arow] = aReg.y;
        As[akq + 2][arow] = aReg.z;
        As[akq + 3][arow] = aReg.w;
        *(float4*)&Bs[brow][bcol] = bReg;
        __syncthreads();

        if (kt + 8 < K) {
            aReg = *(const float4*)(Ap + kt + 8);
            if (MODE == 1) {
                float4 t = *(const float4*)(A2p + kt + 8);
                aReg.x += t.x; aReg.y += t.y; aReg.z += t.z; aReg.w += t.w;
            }
            bReg = *(const float4*)(Bp + (size_t)(kt + 8) * N);
        }

#pragma unroll
        for (int k = 0; k < 8; ++k) {
            float4 a0 = *(const float4*)&As[k][ty * 8];
            float4 a1 = *(const float4*)&As[k][ty * 8 + 4];
            float4 b0 = *(const float4*)&Bs[k][tx * 4];
            float4 b1 = *(const float4*)&Bs[k][64 + tx * 4];
            float am[8] = {a0.x, a0.y, a0.z, a0.w, a1.x, a1.y, a1.z, a1.w};
            float bn[8] = {b0.x, b0.y, b0.z, b0.w, b1.x, b1.y, b1.z, b1.w};
#pragma unroll
            for (int mi = 0; mi < 8; ++mi)
#pragma unroll
                for (int ni = 0; ni < 8; ++ni)
                    acc[mi][ni] += am[mi] * bn[ni];
        }
        __syncthreads();
    }

    // epilogue
    const int c0 = colBase + tx * 4;
    const int c1 = colBase + 64 + tx * 4;
    float4 bia0 = *(const float4*)&bias[c0];
    float4 bia1 = *(const float4*)&bias[c1];

#pragma unroll
    for (int mi = 0; mi < 8; ++mi) {
        int r = rowBase + ty * 8 + mi;
        size_t off;
        if (MODE == 0) off = ((size_t)(r & 1023) * 64 + (size_t)(r >> 10)) * (size_t)N;
        else           off = (size_t)r * (size_t)N;
        float4 v0 = make_float4(acc[mi][0] + bia0.x, acc[mi][1] + bia0.y,
                                acc[mi][2] + bia0.z, acc[mi][3] + bia0.w);
        float4 v1 = make_float4(acc[mi][4] + bia1.x, acc[mi][5] + bia1.y,
                                acc[mi][6] + bia1.z, acc[mi][7] + bia1.w);
        *(float4*)&C[off + c0] = v0;
        *(float4*)&C[off + c1] = v1;
    }
}

// =====================================================================
//  Persistent bidirectional LSTM layer.
//  128 CTAs (1/SM, co-resident): CTA = (dir, 8 c-columns). U slice in SMEM.
// =====================================================================
struct RecSmem {
    float Us[512][32];   // U slice [k][gate*8+q]        64 KB
    float hs[512][64];   // staged h_prev [k][b]        128 KB
    float zsm[64][32];   // z increments  [b][gate*8+q]   8 KB
    float cs[8][64];     // c state       [q][b]          2 KB
};

__device__ __forceinline__ void grid_bar(unsigned int target)
{
    __threadfence();
    __syncthreads();
    if (threadIdx.x == 0) {
        atomicAdd(&g_bar, 1u);
        while (*(volatile unsigned int*)&g_bar < target) { }
    }
    __syncthreads();
}

__global__ void __launch_bounds__(128, 1)
lstm_layer_kernel(const float* __restrict__ Zf, const float* __restrict__ Zb,
                  const float* __restrict__ Uf, const float* __restrict__ Ub,
                  float* __restrict__ hout)
{
    extern __shared__ char sraw[];
    RecSmem* S = (RecSmem*)sraw;

    const int tid = threadIdx.x;
    const int dir = blockIdx.x >> 6;   // 0 fwd, 1 bwd
    const int jb  = blockIdx.x & 63;   // c-column block: cols [jb*8, jb*8+8)
    const float* U = dir ? Ub : Uf;
    const float* Z = dir ? Zb : Zf;

    // load U slice: Us[k][l], l = g*8+q  <-  U[k][g*512 + jb*8 + q]
    for (int idx = tid; idx < 512 * 32; idx += 128) {
        int k = idx >> 5, l = idx & 31;
        S->Us[k][l] = U[(size_t)k * 2048 + (size_t)(l >> 3) * 512 + jb * 8 + (l & 7)];
    }
    for (int idx = tid; idx < 512; idx += 128) (&S->cs[0][0])[idx] = 0.f;
    {
        float* h0 = &g_hst[dir][0][jb * 8][0];
        for (int idx = tid; idx < 512; idx += 128) h0[idx] = 0.f;
    }
    grid_bar(128u);

    const int tx = tid & 7;    // 8 col groups of 4
    const int ty = tid >> 3;   // 16 batch groups of 4
    const int eb = tid >> 1;            // epilogue batch
    const int q0 = (tid & 1) * 4;       // epilogue col-quad within the 8

    for (int s = 0; s < TSTEPS; ++s) {
        const int t = dir ? (TSTEPS - 1 - s) : s;
        const int p = s & 1;

        // prefetch this thread's Z gate biases (hidden under the GEMM)
        const float* Zt = Z + ((size_t)t * 64 + eb) * 2048 + jb * 8 + q0;
        float4 zi4 = *(const float4*)(Zt + 0);
        float4 zf4 = *(const float4*)(Zt + 512);
        float4 zg4 = *(const float4*)(Zt + 1024);
        float4 zo4 = *(const float4*)(Zt + 1536);

        // stage h_prev [512][64] from L2 (bypass L1: cross-SM producer)
        {
            const float4* src = (const float4*)&g_hst[dir][p][0][0];
            float4* dst = (float4*)&S->hs[0][0];
#pragma unroll 8
            for (int i = 0; i < 64; ++i)
                dst[tid + (i << 7)] = __ldcg(src + tid + (i << 7));
        }
        __syncthreads();

        // z += h_prev @ Uslice : [64,512]@[512,32]
        float acc[4][4];
#pragma unroll
        for (int i = 0; i < 4; ++i)
#pragma unroll
            for (int j = 0; j < 4; ++j) acc[i][j] = 0.f;

#pragma unroll 8
        for (int k = 0; k < 512; ++k) {
            float4 hv = *(const float4*)&S->hs[k][ty << 2];
            float4 uv = *(const float4*)&S->Us[k][tx << 2];
            float hm[4] = {hv.x, hv.y, hv.z, hv.w};
            float un[4] = {uv.x, uv.y, uv.z, uv.w};
#pragma unroll
            for (int i = 0; i < 4; ++i)
#pragma unroll
                for (int j = 0; j < 4; ++j)
                    acc[i][j] += hm[i] * un[j];
        }
#pragma unroll
        for (int bi = 0; bi < 4; ++bi)
            *(float4*)&S->zsm[(ty << 2) + bi][tx << 2] =
                make_float4(acc[bi][0], acc[bi][1], acc[bi][2], acc[bi][3]);
        __syncthreads();

        // gate epilogue: each thread owns (b=eb, q=q0..q0+3)
        float zi[4] = {zi4.x, zi4.y, zi4.z, zi4.w};
        float zf[4] = {zf4.x, zf4.y, zf4.z, zf4.w};
        float zg[4] = {zg4.x, zg4.y, zg4.z, zg4.w};
        float zo[4] = {zo4.x, zo4.y, zo4.z, zo4.w};
#pragma unroll
        for (int i2 = 0; i2 < 4; ++i2) {
            int q = q0 + i2;
            float vi = S->zsm[eb][q]      + zi[i2];
            float vf = S->zsm[eb][8 + q]  + zf[i2];
            float vg = S->zsm[eb][16 + q] + zg[i2];
            float vo = S->zsm[eb][24 + q] + zo[i2];
            float ig = 1.f / (1.f + __expf(-vi));
            float fg = 1.f / (1.f + __expf(-vf));
            float gg = tanhf(vg);
            float og = 1.f / (1.f + __expf(-vo));
            float cc = fg * S->cs[q][eb] + ig * gg;
            S->cs[q][eb] = cc;
            float hh = og * tanhf(cc);
            __stcg(&g_hst[dir][p ^ 1][jb * 8 + q][eb], hh);
            hout[((size_t)eb * 1024 + t) * 1024 + dir * 512 + jb * 8 + q] = hh;
        }

        grid_bar(128u * (unsigned)(s + 2));
    }
}

__global__ void reset_bar_kernel() { g_bar = 0u; }

// =====================================================================
extern "C" void kernel_launch(void* const* d_in, const int* in_sizes, int n_in,
                              void* d_out, int out_size)
{
    (void)in_sizes; (void)n_in; (void)out_size;
    const float* x   = (const float*)d_in[0];
    const float* W1f = (const float*)d_in[1];
    const float* U1f = (const float*)d_in[2];
    const float* b1f = (const float*)d_in[3];
    const float* W1b = (const float*)d_in[4];
    const float* U1b = (const float*)d_in[5];
    const float* b1b = (const float*)d_in[6];
    const float* W2f = (const float*)d_in[7];
    const float* U2f = (const float*)d_in[8];
    const float* b2f = (const float*)d_in[9];
    const float* W2b = (const float*)d_in[10];
    const float* U2b = (const float*)d_in[11];
    const float* b2b = (const float*)d_in[12];
    const float* Wd  = (const float*)d_in[13];
    const float* bd  = (const float*)d_in[14];
    float* out = (float*)d_out;

    float *Zf, *Zb, *h1, *h2;
    cudaGetSymbolAddress((void**)&Zf, g_Zf);
    cudaGetSymbolAddress((void**)&Zb, g_Zb);
    cudaGetSymbolAddress((void**)&h1, g_h1);
    cudaGetSymbolAddress((void**)&h2, g_h2);

    cudaFuncSetAttribute(lstm_layer_kernel,
                         cudaFuncAttributeMaxDynamicSharedMemorySize,
                         (int)sizeof(RecSmem));

    dim3 blk(256);
    dim3 gZ(2048 / 128, 65536 / 128);   // (16, 512)
    dim3 gO(512 / 128, 65536 / 128);    // (4, 512)

    // layer 1 input projections
    sgemm_kernel<0><<<gZ, blk>>>(x, nullptr, W1f, b1f, Zf, 512, 2048);
    sgemm_kernel<0><<<gZ, blk>>>(x, nullptr, W1b, b1b, Zb, 512, 2048);

    // layer 1 recurrence
    reset_bar_kernel<<<1, 1>>>();
    lstm_layer_kernel<<<128, 128, sizeof(RecSmem)>>>(Zf, Zb, U1f, U1b, h1);

    // layer 2 input projections (reuse Z buffers)
    sgemm_kernel<0><<<gZ, blk>>>(h1, nullptr, W2f, b2f, Zf, 1024, 2048);
    sgemm_kernel<0><<<gZ, blk>>>(h1, nullptr, W2b, b2b, Zb, 1024, 2048);

    // layer 2 recurrence
    reset_bar_kernel<<<1, 1>>>();
    lstm_layer_kernel<<<128, 128, sizeof(RecSmem)>>>(Zf, Zb, U2f, U2b, h2);

    // out = (h1 + h2) @ Wd + bd
    sgemm_kernel<1><<<gO, blk>>>(h1, h2, Wd, bd, out, 1024, 512);
}

// round 4
// speedup vs baseline: 1.2951x; 1.2951x over previous
#include <cuda_runtime.h>
#include <math.h>
#include <stdint.h>

#define TSTEPS 1024
#define BATCH  64
#define HID    512

// ---------------- scratch (static device allocations; no cudaMalloc) ----------------
__device__ float g_Zf[(size_t)TSTEPS * BATCH * 2048];   // Z fwd  [t][b][4H]
__device__ float g_Zb[(size_t)TSTEPS * BATCH * 2048];   // Z bwd  [t][b][4H] (reused as hsum)
__device__ float g_h1[(size_t)BATCH * TSTEPS * 1024];   // layer1 out [b][t][2H]
__device__ float g_h2[(size_t)BATCH * TSTEPS * 1024];   // layer2 out [b][t][2H]
__device__ float g_xr[(size_t)BATCH * TSTEPS * 512];    // tf32-rounded x
__device__ float g_hst[2][2][HID][BATCH];               // h state [dir][phase][col][b]
__device__ unsigned int g_bar;

// transposed + tf32-rounded weights [N][K]
__device__ float g_Wt1f[2048 * 512];
__device__ float g_Wt1b[2048 * 512];
__device__ float g_Wt2f[2048 * 1024];
__device__ float g_Wt2b[2048 * 1024];
__device__ float g_Wtd [512 * 1024];

__device__ __forceinline__ float to_tf32(float v) {
    float r; asm("cvt.rna.tf32.f32 %0, %1;" : "=f"(r) : "f"(v)); return r;
}
__device__ __forceinline__ uint32_t smem_u32(const void* p) {
    uint32_t a;
    asm("{ .reg .u64 t; cvta.to.shared.u64 t, %1; cvt.u32.u64 %0, t; }" : "=r"(a) : "l"(p));
    return a;
}

// =====================================================================
//  Elementwise helpers
// =====================================================================
__global__ void round_copy_kernel(const float* __restrict__ a, float* __restrict__ o, int n4)
{
    int i = blockIdx.x * blockDim.x + threadIdx.x;
    if (i < n4) {
        float4 v = ((const float4*)a)[i];
        ((float4*)o)[i] = make_float4(to_tf32(v.x), to_tf32(v.y), to_tf32(v.z), to_tf32(v.w));
    }
}
__global__ void add_round_kernel(const float* __restrict__ a, const float* __restrict__ b,
                                 float* __restrict__ o, int n4)
{
    int i = blockIdx.x * blockDim.x + threadIdx.x;
    if (i < n4) {
        float4 va = ((const float4*)a)[i];
        float4 vb = ((const float4*)b)[i];
        ((float4*)o)[i] = make_float4(to_tf32(va.x + vb.x), to_tf32(va.y + vb.y),
                                      to_tf32(va.z + vb.z), to_tf32(va.w + vb.w));
    }
}

// Transpose + tf32-round: Wt[n][k] = rna(W[k][n])
__global__ void transpose_kernel(const float* __restrict__ W, float* __restrict__ Wt,
                                 int K, int N)
{
    __shared__ float tile[32][33];
    int kb = blockIdx.x * 32, nb = blockIdx.y * 32;
    int tx = threadIdx.x, ty = threadIdx.y;
#pragma unroll
    for (int i = ty; i < 32; i += 8)
        tile[i][tx] = W[(size_t)(kb + i) * N + nb + tx];
    __syncthreads();
#pragma unroll
    for (int i = ty; i < 32; i += 8)
        Wt[(size_t)(nb + i) * K + kb + tx] = to_tf32(tile[tx][i]);
}

// =====================================================================
//  TF32 mma.sync GEMM:  C[M,N] = A[M,K] @ Bt[N,K]^T (+bias)
//  SCATTER 1: out layout [t][b][N] (row r -> b=r>>10, t=r&1023)
//  SCATTER 0: out row-major
//  256 threads, tile 128x128x32, cp.async double buffer.
//  SMEM: As[2][128][36], Bs[2][128][36] floats (stride 36 -> conflict-free frags)
// =====================================================================
#define ABUF 4608   // 128*36 floats per buffer

__device__ __forceinline__ void cp16(uint32_t dst, const void* src) {
    asm volatile("cp.async.cg.shared.global [%0], [%1], 16;" :: "r"(dst), "l"(src));
}

template <int SCATTER>
__global__ void __launch_bounds__(256, 2)
mma_gemm_kernel(const float* __restrict__ A, const float* __restrict__ Bt,
                const float* __restrict__ bias, float* __restrict__ C, int K, int N)
{
    extern __shared__ float smf[];
    const int tid = threadIdx.x;
    const int wid = tid >> 5, lane = tid & 31;
    const int warp_m = wid & 1, warp_n = wid >> 1;
    const size_t rowBase = (size_t)blockIdx.y * 128;
    const size_t colBase = (size_t)blockIdx.x * 128;
    const uint32_t smbase = smem_u32(smf);
    const int NS = K >> 5;

    float acc[4][4][4];
#pragma unroll
    for (int mi = 0; mi < 4; ++mi)
#pragma unroll
        for (int ni = 0; ni < 4; ++ni)
#pragma unroll
            for (int r = 0; r < 4; ++r) acc[mi][ni][r] = 0.f;

    // tile loader: 4 x (A 16B + B 16B) per thread, one commit group
    auto cp_tile = [&](int s, int p) {
        const int kt = s << 5;
#pragma unroll
        for (int i = 0; i < 4; ++i) {
            int idx = i * 256 + tid;
            int row = idx >> 3, f4 = idx & 7;
            uint32_t da = smbase + (uint32_t)((p * ABUF + row * 36 + f4 * 4) << 2);
            cp16(da, A + (rowBase + row) * K + kt + f4 * 4);
            uint32_t db = smbase + (uint32_t)(((2 * ABUF) + p * ABUF + row * 36 + f4 * 4) << 2);
            cp16(db, Bt + (colBase + row) * K + kt + f4 * 4);
        }
        asm volatile("cp.async.commit_group;");
    };

    cp_tile(0, 0);
    cp_tile(1, 1);

    const int g = lane >> 2, c = lane & 3;
    const int ar0 = warp_m * 64 + g;
    const int bn0 = warp_n * 32 + g;

    for (int s = 0; s < NS; ++s) {
        const int p = s & 1;
        if (s + 1 < NS) asm volatile("cp.async.wait_group 1;");
        else            asm volatile("cp.async.wait_group 0;");
        __syncthreads();

        const float* Ab = smf + p * ABUF;
        const float* Bb = smf + 2 * ABUF + p * ABUF;

#pragma unroll
        for (int k8 = 0; k8 < 4; ++k8) {
            const int kc = k8 * 8 + c;
            uint32_t a[4][4], b[4][2];
#pragma unroll
            for (int mi = 0; mi < 4; ++mi) {
                const float* base = Ab + (ar0 + mi * 16) * 36 + kc;
                a[mi][0] = __float_as_uint(base[0]);
                a[mi][1] = __float_as_uint(base[8 * 36]);
                a[mi][2] = __float_as_uint(base[4]);
                a[mi][3] = __float_as_uint(base[8 * 36 + 4]);
            }
#pragma unroll
            for (int ni = 0; ni < 4; ++ni) {
                const float* base = Bb + (bn0 + ni * 8) * 36 + kc;
                b[ni][0] = __float_as_uint(base[0]);
                b[ni][1] = __float_as_uint(base[4]);
            }
#pragma unroll
            for (int mi = 0; mi < 4; ++mi)
#pragma unroll
                for (int ni = 0; ni < 4; ++ni)
                    asm volatile(
                        "mma.sync.aligned.m16n8k8.row.col.f32.tf32.tf32.f32 "
                        "{%0,%1,%2,%3}, {%4,%5,%6,%7}, {%8,%9}, {%0,%1,%2,%3};"
                        : "+f"(acc[mi][ni][0]), "+f"(acc[mi][ni][1]),
                          "+f"(acc[mi][ni][2]), "+f"(acc[mi][ni][3])
                        : "r"(a[mi][0]), "r"(a[mi][1]), "r"(a[mi][2]), "r"(a[mi][3]),
                          "r"(b[ni][0]), "r"(b[ni][1]));
        }
        __syncthreads();
        if (s + 2 < NS) cp_tile(s + 2, p);
    }

    // epilogue
    const int c2 = (lane & 3) * 2;
#pragma unroll
    for (int mi = 0; mi < 4; ++mi) {
        size_t r0 = rowBase + warp_m * 64 + mi * 16 + g;
        size_t r8 = r0 + 8;
        size_t off0, off8;
        if (SCATTER) {
            off0 = (((r0 & 1023) << 6) + (r0 >> 10)) * (size_t)N;
            off8 = (((r8 & 1023) << 6) + (r8 >> 10)) * (size_t)N;
        } else {
            off0 = r0 * (size_t)N;
            off8 = r8 * (size_t)N;
        }
#pragma unroll
        for (int ni = 0; ni < 4; ++ni) {
            size_t col = colBase + warp_n * 32 + ni * 8 + c2;
            float2 bv = *(const float2*)&bias[col];
            float2 v0 = make_float2(acc[mi][ni][0] + bv.x, acc[mi][ni][1] + bv.y);
            float2 v1 = make_float2(acc[mi][ni][2] + bv.x, acc[mi][ni][3] + bv.y);
            *(float2*)&C[off0 + col] = v0;
            *(float2*)&C[off8 + col] = v1;
        }
    }
}

// =====================================================================
//  Persistent bidirectional LSTM layer (R1 version; hout tf32-rounded)
// =====================================================================
struct RecSmem {
    float Us[512][32];
    float hs[512][64];
    float zsm[64][32];
    float cs[8][64];
};

__device__ __forceinline__ void grid_bar(unsigned int target)
{
    __threadfence();
    __syncthreads();
    if (threadIdx.x == 0) {
        atomicAdd(&g_bar, 1u);
        while (*(volatile unsigned int*)&g_bar < target) { }
    }
    __syncthreads();
}

__global__ void __launch_bounds__(128, 1)
lstm_layer_kernel(const float* __restrict__ Zf, const float* __restrict__ Zb,
                  const float* __restrict__ Uf, const float* __restrict__ Ub,
                  float* __restrict__ hout)
{
    extern __shared__ char sraw[];
    RecSmem* S = (RecSmem*)sraw;

    const int tid = threadIdx.x;
    const int dir = blockIdx.x >> 6;
    const int jb  = blockIdx.x & 63;
    const float* U = dir ? Ub : Uf;
    const float* Z = dir ? Zb : Zf;

    for (int idx = tid; idx < 512 * 32; idx += 128) {
        int k = idx >> 5, l = idx & 31;
        S->Us[k][l] = U[(size_t)k * 2048 + (size_t)(l >> 3) * 512 + jb * 8 + (l & 7)];
    }
    for (int idx = tid; idx < 512; idx += 128) (&S->cs[0][0])[idx] = 0.f;
    {
        float* h0 = &g_hst[dir][0][jb * 8][0];
        for (int idx = tid; idx < 512; idx += 128) h0[idx] = 0.f;
    }
    grid_bar(128u);

    const int tx = tid & 7;
    const int ty = tid >> 3;
    const int eb = tid >> 1;
    const int q0 = (tid & 1) * 4;

    for (int s = 0; s < TSTEPS; ++s) {
        const int t = dir ? (TSTEPS - 1 - s) : s;
        const int p = s & 1;

        const float* Zt = Z + ((size_t)t * 64 + eb) * 2048 + jb * 8 + q0;
        float4 zi4 = *(const float4*)(Zt + 0);
        float4 zf4 = *(const float4*)(Zt + 512);
        float4 zg4 = *(const float4*)(Zt + 1024);
        float4 zo4 = *(const float4*)(Zt + 1536);

        {
            const float4* src = (const float4*)&g_hst[dir][p][0][0];
            float4* dst = (float4*)&S->hs[0][0];
#pragma unroll 8
            for (int i = 0; i < 64; ++i)
                dst[tid + (i << 7)] = __ldcg(src + tid + (i << 7));
        }
        __syncthreads();

        float acc[4][4];
#pragma unroll
        for (int i = 0; i < 4; ++i)
#pragma unroll
            for (int j = 0; j < 4; ++j) acc[i][j] = 0.f;

#pragma unroll 8
        for (int k = 0; k < 512; ++k) {
            float4 hv = *(const float4*)&S->hs[k][ty << 2];
            float4 uv = *(const float4*)&S->Us[k][tx << 2];
            float hm[4] = {hv.x, hv.y, hv.z, hv.w};
            float un[4] = {uv.x, uv.y, uv.z, uv.w};
#pragma unroll
            for (int i = 0; i < 4; ++i)
#pragma unroll
                for (int j = 0; j < 4; ++j)
                    acc[i][j] += hm[i] * un[j];
        }
#pragma unroll
        for (int bi = 0; bi < 4; ++bi)
            *(float4*)&S->zsm[(ty << 2) + bi][tx << 2] =
                make_float4(acc[bi][0], acc[bi][1], acc[bi][2], acc[bi][3]);
        __syncthreads();

        float zi[4] = {zi4.x, zi4.y, zi4.z, zi4.w};
        float zf[4] = {zf4.x, zf4.y, zf4.z, zf4.w};
        float zg[4] = {zg4.x, zg4.y, zg4.z, zg4.w};
        float zo[4] = {zo4.x, zo4.y, zo4.z, zo4.w};
#pragma unroll
        for (int i2 = 0; i2 < 4; ++i2) {
            int q = q0 + i2;
            float vi = S->zsm[eb][q]      + zi[i2];
            float vf = S->zsm[eb][8 + q]  + zf[i2];
            float vg = S->zsm[eb][16 + q] + zg[i2];
            float vo = S->zsm[eb][24 + q] + zo[i2];
            float ig = 1.f / (1.f + __expf(-vi));
            float fg = 1.f / (1.f + __expf(-vf));
            float gg = tanhf(vg);
            float og = 1.f / (1.f + __expf(-vo));
            float cc = fg * S->cs[q][eb] + ig * gg;
            S->cs[q][eb] = cc;
            float hh = og * tanhf(cc);
            __stcg(&g_hst[dir][p ^ 1][jb * 8 + q][eb], hh);
            hout[((size_t)eb * 1024 + t) * 1024 + dir * 512 + jb * 8 + q] = to_tf32(hh);
        }

        grid_bar(128u * (unsigned)(s + 2));
    }
}

__global__ void reset_bar_kernel() { g_bar = 0u; }

// =====================================================================
extern "C" void kernel_launch(void* const* d_in, const int* in_sizes, int n_in,
                              void* d_out, int out_size)
{
    (void)in_sizes; (void)n_in; (void)out_size;
    const float* x   = (const float*)d_in[0];
    const float* W1f = (const float*)d_in[1];
    const float* U1f = (const float*)d_in[2];
    const float* b1f = (const float*)d_in[3];
    const float* W1b = (const float*)d_in[4];
    const float* U1b = (const float*)d_in[5];
    const float* b1b = (const float*)d_in[6];
    const float* W2f = (const float*)d_in[7];
    const float* U2f = (const float*)d_in[8];
    const float* b2f = (const float*)d_in[9];
    const float* W2b = (const float*)d_in[10];
    const float* U2b = (const float*)d_in[11];
    const float* b2b = (const float*)d_in[12];
    const float* Wd  = (const float*)d_in[13];
    const float* bd  = (const float*)d_in[14];
    float* out = (float*)d_out;

    float *Zf, *Zb, *h1, *h2, *xr;
    float *Wt1f, *Wt1b, *Wt2f, *Wt2b, *Wtd;
    cudaGetSymbolAddress((void**)&Zf, g_Zf);
    cudaGetSymbolAddress((void**)&Zb, g_Zb);
    cudaGetSymbolAddress((void**)&h1, g_h1);
    cudaGetSymbolAddress((void**)&h2, g_h2);
    cudaGetSymbolAddress((void**)&xr, g_xr);
    cudaGetSymbolAddress((void**)&Wt1f, g_Wt1f);
    cudaGetSymbolAddress((void**)&Wt1b, g_Wt1b);
    cudaGetSymbolAddress((void**)&Wt2f, g_Wt2f);
    cudaGetSymbolAddress((void**)&Wt2b, g_Wt2b);
    cudaGetSymbolAddress((void**)&Wtd, g_Wtd);

    cudaFuncSetAttribute(lstm_layer_kernel,
                         cudaFuncAttributeMaxDynamicSharedMemorySize, (int)sizeof(RecSmem));
    const int GEMM_SMEM = 4 * ABUF * 4;   // 73728 B
    cudaFuncSetAttribute(mma_gemm_kernel<0>,
                         cudaFuncAttributeMaxDynamicSharedMemorySize, GEMM_SMEM);
    cudaFuncSetAttribute(mma_gemm_kernel<1>,
                         cudaFuncAttributeMaxDynamicSharedMemorySize, GEMM_SMEM);

    // prep: round x, transpose+round weights
    round_copy_kernel<<<(8388608 + 255) / 256, 256>>>(x, xr, 8388608);
    dim3 tb(32, 8);
    transpose_kernel<<<dim3(512 / 32, 2048 / 32), tb>>>(W1f, Wt1f, 512, 2048);
    transpose_kernel<<<dim3(512 / 32, 2048 / 32), tb>>>(W1b, Wt1b, 512, 2048);
    transpose_kernel<<<dim3(1024 / 32, 2048 / 32), tb>>>(W2f, Wt2f, 1024, 2048);
    transpose_kernel<<<dim3(1024 / 32, 2048 / 32), tb>>>(W2b, Wt2b, 1024, 2048);
    transpose_kernel<<<dim3(1024 / 32, 512 / 32), tb>>>(Wd, Wtd, 1024, 512);

    dim3 blk(256);
    dim3 gZ(2048 / 128, 65536 / 128);   // (16, 512)
    dim3 gO(512 / 128, 65536 / 128);    // (4, 512)

    // layer 1 input projections (tf32 mma.sync)
    mma_gemm_kernel<1><<<gZ, blk, GEMM_SMEM>>>(xr, Wt1f, b1f, Zf, 512, 2048);
    mma_gemm_kernel<1><<<gZ, blk, GEMM_SMEM>>>(xr, Wt1b, b1b, Zb, 512, 2048);

    // layer 1 recurrence
    reset_bar_kernel<<<1, 1>>>();
    lstm_layer_kernel<<<128, 128, sizeof(RecSmem)>>>(Zf, Zb, U1f, U1b, h1);

    // layer 2 input projections
    mma_gemm_kernel<1><<<gZ, blk, GEMM_SMEM>>>(h1, Wt2f, b2f, Zf, 1024, 2048);
    mma_gemm_kernel<1><<<gZ, blk, GEMM_SMEM>>>(h1, Wt2b, b2b, Zb, 1024, 2048);

    // layer 2 recurrence
    reset_bar_kernel<<<1, 1>>>();
    lstm_layer_kernel<<<128, 128, sizeof(RecSmem)>>>(Zf, Zb, U2f, U2b, h2);

    // hsum = rna(h1 + h2) into Zb (free now), then dense head
    add_round_kernel<<<(16777216 + 255) / 256, 256>>>(h1, h2, Zb, 16777216);
    mma_gemm_kernel<0><<<gO, blk, GEMM_SMEM>>>(Zb, Wtd, bd, out, 1024, 512);
}

// round 8
// speedup vs baseline: 1.6280x; 1.2571x over previous
#include <cuda_runtime.h>
#include <math.h>
#include <stdint.h>

#define TSTEPS 1024
#define BATCH  64
#define HID    512

// ---------------- scratch (static device allocations; no cudaMalloc) ----------------
__device__ float g_Zf[(size_t)TSTEPS * BATCH * 2048];   // Z fwd [t][b][4H]; later A_hi
__device__ float g_Zb[(size_t)TSTEPS * BATCH * 2048];   // Z bwd [t][b][4H]; later A_lo
__device__ float g_h1[(size_t)BATCH * TSTEPS * 1024];   // layer1 out [b][t][2H] (tf32)
__device__ float g_h2[(size_t)BATCH * TSTEPS * 1024];   // layer2 out [b][t][2H] (fp32)
__device__ float g_xr[(size_t)BATCH * TSTEPS * 512];    // tf32-rounded x
__device__ float g_hst[2][2][HID][BATCH];               // h state [dir][phase][col][b] (plain, R1-proven)
__device__ unsigned int g_bar;

// transposed + tf32-rounded weights [N][K]
__device__ float g_Wt1f[2048 * 512];
__device__ float g_Wt1b[2048 * 512];
__device__ float g_Wt2f[2048 * 1024];
__device__ float g_Wt2b[2048 * 1024];
__device__ float g_Wtd [512 * 1024];
__device__ float g_WtdLo[512 * 1024];

__device__ __forceinline__ float to_tf32(float v) {
    float r; asm("cvt.rna.tf32.f32 %0, %1;" : "=f"(r) : "f"(v)); return r;
}
__device__ __forceinline__ uint32_t smem_u32(const void* p) {
    uint32_t a;
    asm("{ .reg .u64 t; cvta.to.shared.u64 t, %1; cvt.u32.u64 %0, t; }" : "=r"(a) : "l"(p));
    return a;
}

// =====================================================================
//  Elementwise helpers
// =====================================================================
__global__ void round_copy_kernel(const float* __restrict__ a, float* __restrict__ o, int n4)
{
    int i = blockIdx.x * blockDim.x + threadIdx.x;
    if (i < n4) {
        float4 v = ((const float4*)a)[i];
        ((float4*)o)[i] = make_float4(to_tf32(v.x), to_tf32(v.y), to_tf32(v.z), to_tf32(v.w));
    }
}
// A_hi = tf32(h1+h2), A_lo = tf32((h1+h2)-A_hi)
__global__ void add_split_kernel(const float* __restrict__ a, const float* __restrict__ b,
                                 float* __restrict__ ohi, float* __restrict__ olo, int n4)
{
    int i = blockIdx.x * blockDim.x + threadIdx.x;
    if (i < n4) {
        float4 va = ((const float4*)a)[i];
        float4 vb = ((const float4*)b)[i];
        float s0 = va.x + vb.x, s1 = va.y + vb.y, s2 = va.z + vb.z, s3 = va.w + vb.w;
        float h0 = to_tf32(s0), h1v = to_tf32(s1), h2v = to_tf32(s2), h3 = to_tf32(s3);
        ((float4*)ohi)[i] = make_float4(h0, h1v, h2v, h3);
        ((float4*)olo)[i] = make_float4(to_tf32(s0 - h0), to_tf32(s1 - h1v),
                                        to_tf32(s2 - h2v), to_tf32(s3 - h3));
    }
}

// Transpose + tf32-round: Wt[n][k] = rna(W[k][n])
__global__ void transpose_kernel(const float* __restrict__ W, float* __restrict__ Wt,
                                 int K, int N)
{
    __shared__ float tile[32][33];
    int kb = blockIdx.x * 32, nb = blockIdx.y * 32;
    int tx = threadIdx.x, ty = threadIdx.y;
#pragma unroll
    for (int i = ty; i < 32; i += 8)
        tile[i][tx] = W[(size_t)(kb + i) * N + nb + tx];
    __syncthreads();
#pragma unroll
    for (int i = ty; i < 32; i += 8)
        Wt[(size_t)(nb + i) * K + kb + tx] = to_tf32(tile[tx][i]);
}
// Transpose + split: hi = tf32(w), lo = tf32(w - hi)
__global__ void transpose_split_kernel(const float* __restrict__ W, float* __restrict__ Whi,
                                       float* __restrict__ Wlo, int K, int N)
{
    __shared__ float tile[32][33];
    int kb = blockIdx.x * 32, nb = blockIdx.y * 32;
    int tx = threadIdx.x, ty = threadIdx.y;
#pragma unroll
    for (int i = ty; i < 32; i += 8)
        tile[i][tx] = W[(size_t)(kb + i) * N + nb + tx];
    __syncthreads();
#pragma unroll
    for (int i = ty; i < 32; i += 8) {
        float v = tile[tx][i];
        float hi = to_tf32(v);
        Whi[(size_t)(nb + i) * K + kb + tx] = hi;
        Wlo[(size_t)(nb + i) * K + kb + tx] = to_tf32(v - hi);
    }
}

// =====================================================================
//  TF32 mma.sync GEMM:  C[M,N] = A[M,K] @ Bt[N,K]^T (+bias | +=)
//  (unchanged — validated in R4)
// =====================================================================
#define ABUF 4608   // 128*36 floats per buffer

__device__ __forceinline__ void cp16(uint32_t dst, const void* src) {
    asm volatile("cp.async.cg.shared.global [%0], [%1], 16;" :: "r"(dst), "l"(src));
}

template <int SCATTER, int ACCUM>
__global__ void __launch_bounds__(256, 2)
mma_gemm_kernel(const float* __restrict__ A, const float* __restrict__ Bt,
                const float* __restrict__ bias, float* __restrict__ C, int K, int N)
{
    extern __shared__ float smf[];
    const int tid = threadIdx.x;
    const int wid = tid >> 5, lane = tid & 31;
    const int warp_m = wid & 1, warp_n = wid >> 1;
    const size_t rowBase = (size_t)blockIdx.y * 128;
    const size_t colBase = (size_t)blockIdx.x * 128;
    const uint32_t smbase = smem_u32(smf);
    const int NS = K >> 5;

    float acc[4][4][4];
#pragma unroll
    for (int mi = 0; mi < 4; ++mi)
#pragma unroll
        for (int ni = 0; ni < 4; ++ni)
#pragma unroll
            for (int r = 0; r < 4; ++r) acc[mi][ni][r] = 0.f;

    auto cp_tile = [&](int s, int p) {
        const int kt = s << 5;
#pragma unroll
        for (int i = 0; i < 4; ++i) {
            int idx = i * 256 + tid;
            int row = idx >> 3, f4 = idx & 7;
            uint32_t da = smbase + (uint32_t)((p * ABUF + row * 36 + f4 * 4) << 2);
            cp16(da, A + (rowBase + row) * K + kt + f4 * 4);
            uint32_t db = smbase + (uint32_t)(((2 * ABUF) + p * ABUF + row * 36 + f4 * 4) << 2);
            cp16(db, Bt + (colBase + row) * K + kt + f4 * 4);
        }
        asm volatile("cp.async.commit_group;");
    };

    cp_tile(0, 0);
    cp_tile(1, 1);

    const int g = lane >> 2, c = lane & 3;
    const int ar0 = warp_m * 64 + g;
    const int bn0 = warp_n * 32 + g;

    for (int s = 0; s < NS; ++s) {
        const int p = s & 1;
        if (s + 1 < NS) asm volatile("cp.async.wait_group 1;");
        else            asm volatile("cp.async.wait_group 0;");
        __syncthreads();

        const float* Ab = smf + p * ABUF;
        const float* Bb = smf + 2 * ABUF + p * ABUF;

#pragma unroll
        for (int k8 = 0; k8 < 4; ++k8) {
            const int kc = k8 * 8 + c;
            uint32_t a[4][4], b[4][2];
#pragma unroll
            for (int mi = 0; mi < 4; ++mi) {
                const float* base = Ab + (ar0 + mi * 16) * 36 + kc;
                a[mi][0] = __float_as_uint(base[0]);
                a[mi][1] = __float_as_uint(base[8 * 36]);
                a[mi][2] = __float_as_uint(base[4]);
                a[mi][3] = __float_as_uint(base[8 * 36 + 4]);
            }
#pragma unroll
            for (int ni = 0; ni < 4; ++ni) {
                const float* base = Bb + (bn0 + ni * 8) * 36 + kc;
                b[ni][0] = __float_as_uint(base[0]);
                b[ni][1] = __float_as_uint(base[4]);
            }
#pragma unroll
            for (int mi = 0; mi < 4; ++mi)
#pragma unroll
                for (int ni = 0; ni < 4; ++ni)
                    asm volatile(
                        "mma.sync.aligned.m16n8k8.row.col.f32.tf32.tf32.f32 "
                        "{%0,%1,%2,%3}, {%4,%5,%6,%7}, {%8,%9}, {%0,%1,%2,%3};"
                        : "+f"(acc[mi][ni][0]), "+f"(acc[mi][ni][1]),
                          "+f"(acc[mi][ni][2]), "+f"(acc[mi][ni][3])
                        : "r"(a[mi][0]), "r"(a[mi][1]), "r"(a[mi][2]), "r"(a[mi][3]),
                          "r"(b[ni][0]), "r"(b[ni][1]));
        }
        __syncthreads();
        if (s + 2 < NS) cp_tile(s + 2, p);
    }

    // epilogue
    const int c2 = (lane & 3) * 2;
#pragma unroll
    for (int mi = 0; mi < 4; ++mi) {
        size_t r0 = rowBase + warp_m * 64 + mi * 16 + g;
        size_t r8 = r0 + 8;
        size_t off0, off8;
        if (SCATTER) {
            off0 = (((r0 & 1023) << 6) + (r0 >> 10)) * (size_t)N;
            off8 = (((r8 & 1023) << 6) + (r8 >> 10)) * (size_t)N;
        } else {
            off0 = r0 * (size_t)N;
            off8 = r8 * (size_t)N;
        }
#pragma unroll
        for (int ni = 0; ni < 4; ++ni) {
            size_t col = colBase + warp_n * 32 + ni * 8 + c2;
            float2 v0, v1;
            if (ACCUM) {
                float2 o0 = *(const float2*)&C[off0 + col];
                float2 o1 = *(const float2*)&C[off8 + col];
                v0 = make_float2(acc[mi][ni][0] + o0.x, acc[mi][ni][1] + o0.y);
                v1 = make_float2(acc[mi][ni][2] + o1.x, acc[mi][ni][3] + o1.y);
            } else {
                float2 bv = *(const float2*)&bias[col];
                v0 = make_float2(acc[mi][ni][0] + bv.x, acc[mi][ni][1] + bv.y);
                v1 = make_float2(acc[mi][ni][2] + bv.x, acc[mi][ni][3] + bv.y);
            }
            *(float2*)&C[off0 + col] = v0;
            *(float2*)&C[off8 + col] = v1;
        }
    }
}

// =====================================================================
//  Persistent bidirectional LSTM layer — tensor-core recurrence, v2.
//  h state in PLAIN [col][b] global layout (R1-proven). Per step each
//  warp-pair ks stages cols [ks*128,+128) into SMEM padded [k][72]
//  (B-frag LDS conflict-free). U slice in registers as split-tf32 MMA
//  A-fragments (R4-proven map). 3 compensated MMAs per fragment.
//  SMEM: 36864 (h pad72) + 8448 (zred) floats = 181,248 B.
// =====================================================================
__device__ __forceinline__ void grid_bar(unsigned int target)
{
    __threadfence();
    __syncthreads();
    if (threadIdx.x == 0) {
        atomicAdd(&g_bar, 1u);
        while (*(volatile unsigned int*)&g_bar < target) { }
    }
    __syncthreads();
}

#define LSTM_SMEM ((36864 + 4 * 32 * 66) * 4)

template <int ROUND>
__global__ void __launch_bounds__(256, 1)
lstm_mma_kernel(const float* __restrict__ Zf, const float* __restrict__ Zb,
                const float* __restrict__ Uf, const float* __restrict__ Ub,
                float* __restrict__ hout)
{
    extern __shared__ float sm[];
    float* hs   = sm;           // [4 ks][128 k][72]  (pad-72)
    float* zred = sm + 36864;   // [4 ks][32 l][66]

    const int tid = threadIdx.x;
    const int w = tid >> 5, lane = tid & 31;
    const int g = lane >> 2, c = lane & 3;
    const int ks = w >> 1, mg = w & 1;
    const int dir = blockIdx.x >> 6;
    const int jb  = blockIdx.x & 63;
    const float* U = dir ? Ub : Uf;
    const float* Z = dir ? Zb : Zf;
    float* hst0 = &g_hst[dir][0][0][0];
    float* hst1 = &g_hst[dir][1][0][0];

    // ---- one-time: U A-fragments (split tf32 hi+lo), registers ----
    float uhi[16][4], ulo[16][4];
    {
        const int l0 = mg * 16 + g, l1 = l0 + 8;
        const int gc0 = (l0 >> 3) * 512 + jb * 8 + (l0 & 7);
        const int gc1 = (l1 >> 3) * 512 + jb * 8 + (l1 & 7);
#pragma unroll
        for (int kk = 0; kk < 16; ++kk) {
            int k = ks * 128 + kk * 8;
            float v0 = U[(size_t)(k + c) * 2048 + gc0];
            float v1 = U[(size_t)(k + c) * 2048 + gc1];
            float v2 = U[(size_t)(k + c + 4) * 2048 + gc0];
            float v3 = U[(size_t)(k + c + 4) * 2048 + gc1];
            uhi[kk][0] = to_tf32(v0); ulo[kk][0] = v0 - uhi[kk][0];
            uhi[kk][1] = to_tf32(v1); ulo[kk][1] = v1 - uhi[kk][1];
            uhi[kk][2] = to_tf32(v2); ulo[kk][2] = v2 - uhi[kk][2];
            uhi[kk][3] = to_tf32(v3); ulo[kk][3] = v3 - uhi[kk][3];
        }
    }

    // zero own cols of phase-0 state (cols jb*8..+8, all b)
    for (int i = tid; i < 512; i += 256) hst0[jb * 8 * 64 + i] = 0.f;
    grid_bar(128u);

    // epilogue mapping: thread owns (b=eb, q0) and (b=eb, q0+1)
    const int eb = tid >> 2;
    const int q0 = (tid & 3) * 2;
    float cst0 = 0.f, cst1 = 0.f;
    const int pt = tid & 63;        // lane within warp-pair
    float* hsP = hs + ks * 9216;

    for (int s = 0; s < TSTEPS; ++s) {
        const int t = dir ? (TSTEPS - 1 - s) : s;
        const float* hsrc = (s & 1) ? hst1 : hst0;
        float* hdst = (s & 1) ? hst0 : hst1;

        // Z prefetch (overlaps staging)
        const float* Zt = Z + ((size_t)t * 64 + eb) * 2048 + jb * 8 + q0;
        float2 zi2 = *(const float2*)(Zt + 0);
        float2 zf2 = *(const float2*)(Zt + 512);
        float2 zg2 = *(const float2*)(Zt + 1024);
        float2 zo2 = *(const float2*)(Zt + 1536);

        // ---- stage pair's K-slice: global [col][b] -> smem [k][72] ----
        {
            const float4* src = (const float4*)(hsrc + ks * 8192);
#pragma unroll 8
            for (int i = 0; i < 32; ++i) {
                int idx = i * 64 + pt;          // 0..2047 float4
                int kl = idx >> 4, q4 = idx & 15;
                float4 v = __ldcg(src + idx);
                *(float4*)&hsP[kl * 72 + q4 * 4] = v;
            }
        }
        __syncthreads();

        // ---- MMA: z[l=mg*16..+16][b=0..63] over k in [ks*128,+128) ----
        float acc[8][4];
#pragma unroll
        for (int nt = 0; nt < 8; ++nt)
#pragma unroll
            for (int r = 0; r < 4; ++r) acc[nt][r] = 0.f;

#pragma unroll
        for (int kk = 0; kk < 16; ++kk) {
            uint32_t ah0 = __float_as_uint(uhi[kk][0]), ah1 = __float_as_uint(uhi[kk][1]);
            uint32_t ah2 = __float_as_uint(uhi[kk][2]), ah3 = __float_as_uint(uhi[kk][3]);
            uint32_t al0 = __float_as_uint(ulo[kk][0]), al1 = __float_as_uint(ulo[kk][1]);
            uint32_t al2 = __float_as_uint(ulo[kk][2]), al3 = __float_as_uint(ulo[kk][3]);
            const float* rowA = hsP + (kk * 8 + c) * 72;
            const float* rowB = rowA + 4 * 72;
#pragma unroll
            for (int nt = 0; nt < 8; ++nt) {
                float b0f = rowA[nt * 8 + g];       // h[k+c][b]
                float b1f = rowB[nt * 8 + g];       // h[k+c+4][b]
                float bh0 = to_tf32(b0f), bh1 = to_tf32(b1f);
                float bl0 = b0f - bh0,    bl1 = b1f - bh1;
                asm volatile(
                    "mma.sync.aligned.m16n8k8.row.col.f32.tf32.tf32.f32 "
                    "{%0,%1,%2,%3}, {%4,%5,%6,%7}, {%8,%9}, {%0,%1,%2,%3};"
                    : "+f"(acc[nt][0]), "+f"(acc[nt][1]), "+f"(acc[nt][2]), "+f"(acc[nt][3])
                    : "r"(ah0), "r"(ah1), "r"(ah2), "r"(ah3),
                      "r"(__float_as_uint(bh0)), "r"(__float_as_uint(bh1)));
                asm volatile(
                    "mma.sync.aligned.m16n8k8.row.col.f32.tf32.tf32.f32 "
                    "{%0,%1,%2,%3}, {%4,%5,%6,%7}, {%8,%9}, {%0,%1,%2,%3};"
                    : "+f"(acc[nt][0]), "+f"(acc[nt][1]), "+f"(acc[nt][2]), "+f"(acc[nt][3])
                    : "r"(ah0), "r"(ah1), "r"(ah2), "r"(ah3),
                      "r"(__float_as_uint(bl0)), "r"(__float_as_uint(bl1)));
                asm volatile(
                    "mma.sync.aligned.m16n8k8.row.col.f32.tf32.tf32.f32 "
                    "{%0,%1,%2,%3}, {%4,%5,%6,%7}, {%8,%9}, {%0,%1,%2,%3};"
                    : "+f"(acc[nt][0]), "+f"(acc[nt][1]), "+f"(acc[nt][2]), "+f"(acc[nt][3])
                    : "r"(al0), "r"(al1), "r"(al2), "r"(al3),
                      "r"(__float_as_uint(bh0)), "r"(__float_as_uint(bh1)));
            }
        }

        // ---- store partials: zred[ks][l][b] ----
#pragma unroll
        for (int nt = 0; nt < 8; ++nt) {
            int l0 = mg * 16 + g;
            int n0 = nt * 8 + c * 2;
            *(float2*)&zred[(ks * 32 + l0) * 66 + n0]     = make_float2(acc[nt][0], acc[nt][1]);
            *(float2*)&zred[(ks * 32 + l0 + 8) * 66 + n0] = make_float2(acc[nt][2], acc[nt][3]);
        }
        __syncthreads();

        // ---- gate epilogue: 2 cells (eb, q0), (eb, q0+1) per thread ----
        {
            float vi0 = zi2.x, vi1 = zi2.y, vf0 = zf2.x, vf1 = zf2.y;
            float vg0 = zg2.x, vg1 = zg2.y, vo0 = zo2.x, vo1 = zo2.y;
#pragma unroll
            for (int k = 0; k < 4; ++k) {
                vi0 += zred[(k * 32 + q0)      * 66 + eb];
                vi1 += zred[(k * 32 + q0 + 1)  * 66 + eb];
                vf0 += zred[(k * 32 + 8 + q0)  * 66 + eb];
                vf1 += zred[(k * 32 + 9 + q0)  * 66 + eb];
                vg0 += zred[(k * 32 + 16 + q0) * 66 + eb];
                vg1 += zred[(k * 32 + 17 + q0) * 66 + eb];
                vo0 += zred[(k * 32 + 24 + q0) * 66 + eb];
                vo1 += zred[(k * 32 + 25 + q0) * 66 + eb];
            }
            float ig0 = 1.f / (1.f + __expf(-vi0));
            float ig1 = 1.f / (1.f + __expf(-vi1));
            float fg0 = 1.f / (1.f + __expf(-vf0));
            float fg1 = 1.f / (1.f + __expf(-vf1));
            float gg0 = tanhf(vg0), gg1 = tanhf(vg1);
            float og0 = 1.f / (1.f + __expf(-vo0));
            float og1 = 1.f / (1.f + __expf(-vo1));
            cst0 = fg0 * cst0 + ig0 * gg0;
            cst1 = fg1 * cst1 + ig1 * gg1;
            float hh0 = og0 * tanhf(cst0);
            float hh1 = og1 * tanhf(cst1);

            // plain [col][b] state store (R1-proven layout)
            __stcg(&hdst[(jb * 8 + q0) * 64 + eb],     hh0);
            __stcg(&hdst[(jb * 8 + q0 + 1) * 64 + eb], hh1);

            size_t ho = ((size_t)eb * 1024 + t) * 1024 + dir * 512 + jb * 8 + q0;
            if (ROUND) {
                hout[ho]     = to_tf32(hh0);
                hout[ho + 1] = to_tf32(hh1);
            } else {
                hout[ho]     = hh0;
                hout[ho + 1] = hh1;
            }
        }

        grid_bar(128u * (unsigned)(s + 2));
    }
}

__global__ void reset_bar_kernel() { g_bar = 0u; }

// =====================================================================
extern "C" void kernel_launch(void* const* d_in, const int* in_sizes, int n_in,
                              void* d_out, int out_size)
{
    (void)in_sizes; (void)n_in; (void)out_size;
    const float* x   = (const float*)d_in[0];
    const float* W1f = (const float*)d_in[1];
    const float* U1f = (const float*)d_in[2];
    const float* b1f = (const float*)d_in[3];
    const float* W1b = (const float*)d_in[4];
    const float* U1b = (const float*)d_in[5];
    const float* b1b = (const float*)d_in[6];
    const float* W2f = (const float*)d_in[7];
    const float* U2f = (const float*)d_in[8];
    const float* b2f = (const float*)d_in[9];
    const float* W2b = (const float*)d_in[10];
    const float* U2b = (const float*)d_in[11];
    const float* b2b = (const float*)d_in[12];
    const float* Wd  = (const float*)d_in[13];
    const float* bd  = (const float*)d_in[14];
    float* out = (float*)d_out;

    float *Zf, *Zb, *h1, *h2, *xr;
    float *Wt1f, *Wt1b, *Wt2f, *Wt2b, *Wtd, *WtdLo;
    cudaGetSymbolAddress((void**)&Zf, g_Zf);
    cudaGetSymbolAddress((void**)&Zb, g_Zb);
    cudaGetSymbolAddress((void**)&h1, g_h1);
    cudaGetSymbolAddress((void**)&h2, g_h2);
    cudaGetSymbolAddress((void**)&xr, g_xr);
    cudaGetSymbolAddress((void**)&Wt1f, g_Wt1f);
    cudaGetSymbolAddress((void**)&Wt1b, g_Wt1b);
    cudaGetSymbolAddress((void**)&Wt2f, g_Wt2f);
    cudaGetSymbolAddress((void**)&Wt2b, g_Wt2b);
    cudaGetSymbolAddress((void**)&Wtd, g_Wtd);
    cudaGetSymbolAddress((void**)&WtdLo, g_WtdLo);

    const int GEMM_SMEM = 4 * ABUF * 4;
    cudaFuncSetAttribute(mma_gemm_kernel<0, 0>, cudaFuncAttributeMaxDynamicSharedMemorySize, GEMM_SMEM);
    cudaFuncSetAttribute(mma_gemm_kernel<0, 1>, cudaFuncAttributeMaxDynamicSharedMemorySize, GEMM_SMEM);
    cudaFuncSetAttribute(mma_gemm_kernel<1, 0>, cudaFuncAttributeMaxDynamicSharedMemorySize, GEMM_SMEM);
    cudaFuncSetAttribute(lstm_mma_kernel<0>, cudaFuncAttributeMaxDynamicSharedMemorySize, LSTM_SMEM);
    cudaFuncSetAttribute(lstm_mma_kernel<1>, cudaFuncAttributeMaxDynamicSharedMemorySize, LSTM_SMEM);

    // prep
    round_copy_kernel<<<(8388608 + 255) / 256, 256>>>(x, xr, 8388608);
    dim3 tb(32, 8);
    transpose_kernel<<<dim3(512 / 32, 2048 / 32), tb>>>(W1f, Wt1f, 512, 2048);
    transpose_kernel<<<dim3(512 / 32, 2048 / 32), tb>>>(W1b, Wt1b, 512, 2048);
    transpose_kernel<<<dim3(1024 / 32, 2048 / 32), tb>>>(W2f, Wt2f, 1024, 2048);
    transpose_kernel<<<dim3(1024 / 32, 2048 / 32), tb>>>(W2b, Wt2b, 1024, 2048);
    transpose_split_kernel<<<dim3(1024 / 32, 512 / 32), tb>>>(Wd, Wtd, WtdLo, 1024, 512);

    dim3 blk(256);
    dim3 gZ(2048 / 128, 65536 / 128);
    dim3 gO(512 / 128, 65536 / 128);

    // layer 1 input projections
    mma_gemm_kernel<1, 0><<<gZ, blk, GEMM_SMEM>>>(xr, Wt1f, b1f, Zf, 512, 2048);
    mma_gemm_kernel<1, 0><<<gZ, blk, GEMM_SMEM>>>(xr, Wt1b, b1b, Zb, 512, 2048);

    // layer 1 recurrence (tensor cores)
    reset_bar_kernel<<<1, 1>>>();
    lstm_mma_kernel<1><<<128, 256, LSTM_SMEM>>>(Zf, Zb, U1f, U1b, h1);

    // layer 2 input projections
    mma_gemm_kernel<1, 0><<<gZ, blk, GEMM_SMEM>>>(h1, Wt2f, b2f, Zf, 1024, 2048);
    mma_gemm_kernel<1, 0><<<gZ, blk, GEMM_SMEM>>>(h1, Wt2b, b2b, Zb, 1024, 2048);

    // layer 2 recurrence
    reset_bar_kernel<<<1, 1>>>();
    lstm_mma_kernel<0><<<128, 256, LSTM_SMEM>>>(Zf, Zb, U2f, U2b, h2);

    // dense head, 3-term split: out = (h1+h2)@Wd + bd
    // h1+h2 is 64*1024*1024 = 67,108,864 floats = 16,777,216 float4  (R6/R7 bug: was /4 again)
    add_split_kernel<<<(16777216 + 255) / 256, 256>>>(h1, h2, Zf, Zb, 16777216);
    mma_gemm_kernel<0, 0><<<gO, blk, GEMM_SMEM>>>(Zf, Wtd,   bd, out, 1024, 512);
    mma_gemm_kernel<0, 1><<<gO, blk, GEMM_SMEM>>>(Zb, Wtd,   bd, out, 1024, 512);
    mma_gemm_kernel<0, 1><<<gO, blk, GEMM_SMEM>>>(Zf, WtdLo, bd, out, 1024, 512);
}

// round 9
// speedup vs baseline: 1.6709x; 1.0264x over previous
#include <cuda_runtime.h>
#include <math.h>
#include <stdint.h>

#define TSTEPS 1024
#define BATCH  64
#define HID    512

// ---------------- scratch (static device allocations; no cudaMalloc) ----------------
__device__ float g_Zf[(size_t)TSTEPS * BATCH * 2048];   // Z fwd [t][b][4H]; later A_hi
__device__ float g_Zb[(size_t)TSTEPS * BATCH * 2048];   // Z bwd [t][b][4H]; later A_lo
__device__ float g_h1[(size_t)BATCH * TSTEPS * 1024];   // layer1 out [b][t][2H] (tf32)
__device__ float g_h2[(size_t)BATCH * TSTEPS * 1024];   // layer2 out [b][t][2H] (fp32)
__device__ float g_xr[(size_t)BATCH * TSTEPS * 512];    // tf32-rounded x
__device__ float g_hst[2][2][HID][BATCH];               // h state [dir][phase][col][b]
__device__ unsigned int g_bar;

// transposed + tf32-rounded weights [N][K]
__device__ float g_Wt1f[2048 * 512];
__device__ float g_Wt1b[2048 * 512];
__device__ float g_Wt2f[2048 * 1024];
__device__ float g_Wt2b[2048 * 1024];
__device__ float g_Wtd [512 * 1024];
__device__ float g_WtdLo[512 * 1024];

__device__ __forceinline__ float to_tf32(float v) {
    float r; asm("cvt.rna.tf32.f32 %0, %1;" : "=f"(r) : "f"(v)); return r;
}
__device__ __forceinline__ uint32_t smem_u32(const void* p) {
    uint32_t a;
    asm("{ .reg .u64 t; cvta.to.shared.u64 t, %1; cvt.u32.u64 %0, t; }" : "=r"(a) : "l"(p));
    return a;
}
__device__ __forceinline__ float fsigm(float x) { return 1.f / (1.f + __expf(-x)); }
__device__ __forceinline__ float ftanh(float x) {
    float e = __expf(2.f * x);
    return 1.f - __fdividef(2.f, e + 1.f);
}

// =====================================================================
//  Fused prep kernel: blockIdx.y selects task.
//  0: xr = rna(x)   1..4: transpose+round W1f/W1b/W2f/W2b   5: split Wd
// =====================================================================
__global__ void prep_all_kernel(
    const float* __restrict__ x,   float* __restrict__ xr,
    const float* __restrict__ W1f, float* __restrict__ Wt1f,
    const float* __restrict__ W1b, float* __restrict__ Wt1b,
    const float* __restrict__ W2f, float* __restrict__ Wt2f,
    const float* __restrict__ W2b, float* __restrict__ Wt2b,
    const float* __restrict__ Wd,  float* __restrict__ Wtd, float* __restrict__ WtdLo)
{
    const int task = blockIdx.y;
    if (task == 0) {
        const int n4 = 8388608;
        for (int i = blockIdx.x * 256 + threadIdx.x; i < n4; i += 2048 * 256) {
            float4 v = ((const float4*)x)[i];
            ((float4*)xr)[i] = make_float4(to_tf32(v.x), to_tf32(v.y),
                                           to_tf32(v.z), to_tf32(v.w));
        }
        return;
    }
    const float* W; float* Wt; float* Wlo = nullptr; int K, N;
    switch (task) {
        case 1: W = W1f; Wt = Wt1f; K = 512;  N = 2048; break;
        case 2: W = W1b; Wt = Wt1b; K = 512;  N = 2048; break;
        case 3: W = W2f; Wt = Wt2f; K = 1024; N = 2048; break;
        case 4: W = W2b; Wt = Wt2b; K = 1024; N = 2048; break;
        default: W = Wd; Wt = Wtd; Wlo = WtdLo; K = 1024; N = 512; break;
    }
    const int nkb = K / 32;
    const int total = nkb * (N / 32);
    const int bx = blockIdx.x;
    if (bx >= total) return;
    __shared__ float tile[32][33];
    const int kb = (bx % nkb) * 32, nb = (bx / nkb) * 32;
    const int tx = threadIdx.x & 31, ty = threadIdx.x >> 5;
#pragma unroll
    for (int i = ty; i < 32; i += 8)
        tile[i][tx] = W[(size_t)(kb + i) * N + nb + tx];
    __syncthreads();
#pragma unroll
    for (int i = ty; i < 32; i += 8) {
        float v = tile[tx][i];
        float hi = to_tf32(v);
        Wt[(size_t)(nb + i) * K + kb + tx] = hi;
        if (Wlo) Wlo[(size_t)(nb + i) * K + kb + tx] = to_tf32(v - hi);
    }
}

// A_hi = tf32(h1+h2), A_lo = tf32((h1+h2)-A_hi)
__global__ void add_split_kernel(const float* __restrict__ a, const float* __restrict__ b,
                                 float* __restrict__ ohi, float* __restrict__ olo, int n4)
{
    int i = blockIdx.x * blockDim.x + threadIdx.x;
    if (i < n4) {
        float4 va = ((const float4*)a)[i];
        float4 vb = ((const float4*)b)[i];
        float s0 = va.x + vb.x, s1 = va.y + vb.y, s2 = va.z + vb.z, s3 = va.w + vb.w;
        float h0 = to_tf32(s0), h1v = to_tf32(s1), h2v = to_tf32(s2), h3 = to_tf32(s3);
        ((float4*)ohi)[i] = make_float4(h0, h1v, h2v, h3);
        ((float4*)olo)[i] = make_float4(to_tf32(s0 - h0), to_tf32(s1 - h1v),
                                        to_tf32(s2 - h2v), to_tf32(s3 - h3));
    }
}

// =====================================================================
//  TF32 mma.sync GEMM (validated R4):  C = A @ Bt^T (+bias | +=)
// =====================================================================
#define ABUF 4608   // 128*36 floats per buffer

__device__ __forceinline__ void cp16(uint32_t dst, const void* src) {
    asm volatile("cp.async.cg.shared.global [%0], [%1], 16;" :: "r"(dst), "l"(src));
}

template <int SCATTER, int ACCUM>
__global__ void __launch_bounds__(256, 2)
mma_gemm_kernel(const float* __restrict__ A, const float* __restrict__ Bt,
                const float* __restrict__ bias, float* __restrict__ C, int K, int N)
{
    extern __shared__ float smf[];
    const int tid = threadIdx.x;
    const int wid = tid >> 5, lane = tid & 31;
    const int warp_m = wid & 1, warp_n = wid >> 1;
    const size_t rowBase = (size_t)blockIdx.y * 128;
    const size_t colBase = (size_t)blockIdx.x * 128;
    const uint32_t smbase = smem_u32(smf);
    const int NS = K >> 5;

    float acc[4][4][4];
#pragma unroll
    for (int mi = 0; mi < 4; ++mi)
#pragma unroll
        for (int ni = 0; ni < 4; ++ni)
#pragma unroll
            for (int r = 0; r < 4; ++r) acc[mi][ni][r] = 0.f;

    auto cp_tile = [&](int s, int p) {
        const int kt = s << 5;
#pragma unroll
        for (int i = 0; i < 4; ++i) {
            int idx = i * 256 + tid;
            int row = idx >> 3, f4 = idx & 7;
            uint32_t da = smbase + (uint32_t)((p * ABUF + row * 36 + f4 * 4) << 2);
            cp16(da, A + (rowBase + row) * K + kt + f4 * 4);
            uint32_t db = smbase + (uint32_t)(((2 * ABUF) + p * ABUF + row * 36 + f4 * 4) << 2);
            cp16(db, Bt + (colBase + row) * K + kt + f4 * 4);
        }
        asm volatile("cp.async.commit_group;");
    };

    cp_tile(0, 0);
    cp_tile(1, 1);

    const int g = lane >> 2, c = lane & 3;
    const int ar0 = warp_m * 64 + g;
    const int bn0 = warp_n * 32 + g;

    for (int s = 0; s < NS; ++s) {
        const int p = s & 1;
        if (s + 1 < NS) asm volatile("cp.async.wait_group 1;");
        else            asm volatile("cp.async.wait_group 0;");
        __syncthreads();

        const float* Ab = smf + p * ABUF;
        const float* Bb = smf + 2 * ABUF + p * ABUF;

#pragma unroll
        for (int k8 = 0; k8 < 4; ++k8) {
            const int kc = k8 * 8 + c;
            uint32_t a[4][4], b[4][2];
#pragma unroll
            for (int mi = 0; mi < 4; ++mi) {
                const float* base = Ab + (ar0 + mi * 16) * 36 + kc;
                a[mi][0] = __float_as_uint(base[0]);
                a[mi][1] = __float_as_uint(base[8 * 36]);
                a[mi][2] = __float_as_uint(base[4]);
                a[mi][3] = __float_as_uint(base[8 * 36 + 4]);
            }
#pragma unroll
            for (int ni = 0; ni < 4; ++ni) {
                const float* base = Bb + (bn0 + ni * 8) * 36 + kc;
                b[ni][0] = __float_as_uint(base[0]);
                b[ni][1] = __float_as_uint(base[4]);
            }
#pragma unroll
            for (int mi = 0; mi < 4; ++mi)
#pragma unroll
                for (int ni = 0; ni < 4; ++ni)
                    asm volatile(
                        "mma.sync.aligned.m16n8k8.row.col.f32.tf32.tf32.f32 "
                        "{%0,%1,%2,%3}, {%4,%5,%6,%7}, {%8,%9}, {%0,%1,%2,%3};"
                        : "+f"(acc[mi][ni][0]), "+f"(acc[mi][ni][1]),
                          "+f"(acc[mi][ni][2]), "+f"(acc[mi][ni][3])
                        : "r"(a[mi][0]), "r"(a[mi][1]), "r"(a[mi][2]), "r"(a[mi][3]),
                          "r"(b[ni][0]), "r"(b[ni][1]));
        }
        __syncthreads();
        if (s + 2 < NS) cp_tile(s + 2, p);
    }

    const int c2 = (lane & 3) * 2;
#pragma unroll
    for (int mi = 0; mi < 4; ++mi) {
        size_t r0 = rowBase + warp_m * 64 + mi * 16 + g;
        size_t r8 = r0 + 8;
        size_t off0, off8;
        if (SCATTER) {
            off0 = (((r0 & 1023) << 6) + (r0 >> 10)) * (size_t)N;
            off8 = (((r8 & 1023) << 6) + (r8 >> 10)) * (size_t)N;
        } else {
            off0 = r0 * (size_t)N;
            off8 = r8 * (size_t)N;
        }
#pragma unroll
        for (int ni = 0; ni < 4; ++ni) {
            size_t col = colBase + warp_n * 32 + ni * 8 + c2;
            float2 v0, v1;
            if (ACCUM) {
                float2 o0 = *(const float2*)&C[off0 + col];
                float2 o1 = *(const float2*)&C[off8 + col];
                v0 = make_float2(acc[mi][ni][0] + o0.x, acc[mi][ni][1] + o0.y);
                v1 = make_float2(acc[mi][ni][2] + o1.x, acc[mi][ni][3] + o1.y);
            } else {
                float2 bv = *(const float2*)&bias[col];
                v0 = make_float2(acc[mi][ni][0] + bv.x, acc[mi][ni][1] + bv.y);
                v1 = make_float2(acc[mi][ni][2] + bv.x, acc[mi][ni][3] + bv.y);
            }
            *(float2*)&C[off0 + col] = v0;
            *(float2*)&C[off8 + col] = v1;
        }
    }
}

// =====================================================================
//  Persistent bidirectional LSTM layer — tensor-core recurrence.
//  (R8-validated structure; this round: split arrive/wait barrier with
//  hout stores + next-Z prefetch in the window, fast tanh epilogue.)
// =====================================================================
__device__ __forceinline__ void bar_arrive()
{
    __threadfence();
    __syncthreads();
    if (threadIdx.x == 0) atomicAdd(&g_bar, 1u);
}
__device__ __forceinline__ void bar_wait(unsigned int target)
{
    if (threadIdx.x == 0)
        while (*(volatile unsigned int*)&g_bar < target) { }
    __syncthreads();
}

#define LSTM_SMEM ((36864 + 4 * 32 * 66) * 4)

template <int ROUND>
__global__ void __launch_bounds__(256, 1)
lstm_mma_kernel(const float* __restrict__ Zf, const float* __restrict__ Zb,
                const float* __restrict__ Uf, const float* __restrict__ Ub,
                float* __restrict__ hout)
{
    extern __shared__ float sm[];
    float* hs   = sm;           // [4 ks][128 k][72]  (pad-72)
    float* zred = sm + 36864;   // [4 ks][32 l][66]

    const int tid = threadIdx.x;
    const int w = tid >> 5, lane = tid & 31;
    const int g = lane >> 2, c = lane & 3;
    const int ks = w >> 1, mg = w & 1;
    const int dir = blockIdx.x >> 6;
    const int jb  = blockIdx.x & 63;
    const float* U = dir ? Ub : Uf;
    const float* Z = dir ? Zb : Zf;
    float* hst0 = &g_hst[dir][0][0][0];
    float* hst1 = &g_hst[dir][1][0][0];

    // ---- one-time: U A-fragments (split tf32 hi+lo), registers ----
    float uhi[16][4], ulo[16][4];
    {
        const int l0 = mg * 16 + g, l1 = l0 + 8;
        const int gc0 = (l0 >> 3) * 512 + jb * 8 + (l0 & 7);
        const int gc1 = (l1 >> 3) * 512 + jb * 8 + (l1 & 7);
#pragma unroll
        for (int kk = 0; kk < 16; ++kk) {
            int k = ks * 128 + kk * 8;
            float v0 = U[(size_t)(k + c) * 2048 + gc0];
            float v1 = U[(size_t)(k + c) * 2048 + gc1];
            float v2 = U[(size_t)(k + c + 4) * 2048 + gc0];
            float v3 = U[(size_t)(k + c + 4) * 2048 + gc1];
            uhi[kk][0] = to_tf32(v0); ulo[kk][0] = v0 - uhi[kk][0];
            uhi[kk][1] = to_tf32(v1); ulo[kk][1] = v1 - uhi[kk][1];
            uhi[kk][2] = to_tf32(v2); ulo[kk][2] = v2 - uhi[kk][2];
            uhi[kk][3] = to_tf32(v3); ulo[kk][3] = v3 - uhi[kk][3];
        }
    }

    // zero own cols of phase-0 state
    for (int i = tid; i < 512; i += 256) hst0[jb * 8 * 64 + i] = 0.f;
    bar_arrive();
    bar_wait(128u);

    // epilogue mapping: thread owns (b=eb, q0) and (b=eb, q0+1)
    const int eb = tid >> 2;
    const int q0 = (tid & 3) * 2;
    float cst0 = 0.f, cst1 = 0.f;
    const int pt = tid & 63;
    float* hsP = hs + ks * 9216;

    // prologue Z prefetch for s=0
    float2 zi2, zf2, zg2, zo2;
    {
        int t0 = dir ? (TSTEPS - 1) : 0;
        const float* Zt = Z + ((size_t)t0 * 64 + eb) * 2048 + jb * 8 + q0;
        zi2 = *(const float2*)(Zt + 0);
        zf2 = *(const float2*)(Zt + 512);
        zg2 = *(const float2*)(Zt + 1024);
        zo2 = *(const float2*)(Zt + 1536);
    }

    for (int s = 0; s < TSTEPS; ++s) {
        const int t = dir ? (TSTEPS - 1 - s) : s;
        const float* hsrc = (s & 1) ? hst1 : hst0;
        float* hdst = (s & 1) ? hst0 : hst1;

        // ---- stage pair's K-slice: global [col][b] -> smem [k][72] ----
        {
            const float4* src = (const float4*)(hsrc + ks * 8192);
#pragma unroll 8
            for (int i = 0; i < 32; ++i) {
                int idx = i * 64 + pt;          // 0..2047 float4
                int kl = idx >> 4, q4 = idx & 15;
                float4 v = __ldcg(src + idx);
                *(float4*)&hsP[kl * 72 + q4 * 4] = v;
            }
        }
        __syncthreads();

        // ---- MMA: z[l=mg*16..+16][b=0..63] over k in [ks*128,+128) ----
        float acc[8][4];
#pragma unroll
        for (int nt = 0; nt < 8; ++nt)
#pragma unroll
            for (int r = 0; r < 4; ++r) acc[nt][r] = 0.f;

#pragma unroll
        for (int kk = 0; kk < 16; ++kk) {
            uint32_t ah0 = __float_as_uint(uhi[kk][0]), ah1 = __float_as_uint(uhi[kk][1]);
            uint32_t ah2 = __float_as_uint(uhi[kk][2]), ah3 = __float_as_uint(uhi[kk][3]);
            uint32_t al0 = __float_as_uint(ulo[kk][0]), al1 = __float_as_uint(ulo[kk][1]);
            uint32_t al2 = __float_as_uint(ulo[kk][2]), al3 = __float_as_uint(ulo[kk][3]);
            const float* rowA = hsP + (kk * 8 + c) * 72;
            const float* rowB = rowA + 4 * 72;
#pragma unroll
            for (int nt = 0; nt < 8; ++nt) {
                float b0f = rowA[nt * 8 + g];
                float b1f = rowB[nt * 8 + g];
                float bh0 = to_tf32(b0f), bh1 = to_tf32(b1f);
                float bl0 = b0f - bh0,    bl1 = b1f - bh1;
                asm volatile(
                    "mma.sync.aligned.m16n8k8.row.col.f32.tf32.tf32.f32 "
                    "{%0,%1,%2,%3}, {%4,%5,%6,%7}, {%8,%9}, {%0,%1,%2,%3};"
                    : "+f"(acc[nt][0]), "+f"(acc[nt][1]), "+f"(acc[nt][2]), "+f"(acc[nt][3])
                    : "r"(ah0), "r"(ah1), "r"(ah2), "r"(ah3),
                      "r"(__float_as_uint(bh0)), "r"(__float_as_uint(bh1)));
                asm volatile(
                    "mma.sync.aligned.m16n8k8.row.col.f32.tf32.tf32.f32 "
                    "{%0,%1,%2,%3}, {%4,%5,%6,%7}, {%8,%9}, {%0,%1,%2,%3};"
                    : "+f"(acc[nt][0]), "+f"(acc[nt][1]), "+f"(acc[nt][2]), "+f"(acc[nt][3])
                    : "r"(ah0), "r"(ah1), "r"(ah2), "r"(ah3),
                      "r"(__float_as_uint(bl0)), "r"(__float_as_uint(bl1)));
                asm volatile(
                    "mma.sync.aligned.m16n8k8.row.col.f32.tf32.tf32.f32 "
                    "{%0,%1,%2,%3}, {%4,%5,%6,%7}, {%8,%9}, {%0,%1,%2,%3};"
                    : "+f"(acc[nt][0]), "+f"(acc[nt][1]), "+f"(acc[nt][2]), "+f"(acc[nt][3])
                    : "r"(al0), "r"(al1), "r"(al2), "r"(al3),
                      "r"(__float_as_uint(bh0)), "r"(__float_as_uint(bh1)));
            }
        }

        // ---- store partials: zred[ks][l][b] ----
#pragma unroll
        for (int nt = 0; nt < 8; ++nt) {
            int l0 = mg * 16 + g;
            int n0 = nt * 8 + c * 2;
            *(float2*)&zred[(ks * 32 + l0) * 66 + n0]     = make_float2(acc[nt][0], acc[nt][1]);
            *(float2*)&zred[(ks * 32 + l0 + 8) * 66 + n0] = make_float2(acc[nt][2], acc[nt][3]);
        }
        __syncthreads();

        // ---- gate epilogue: 2 cells (eb, q0), (eb, q0+1) per thread ----
        float hh0, hh1;
        {
            float vi0 = zi2.x, vi1 = zi2.y, vf0 = zf2.x, vf1 = zf2.y;
            float vg0 = zg2.x, vg1 = zg2.y, vo0 = zo2.x, vo1 = zo2.y;
#pragma unroll
            for (int k = 0; k < 4; ++k) {
                vi0 += zred[(k * 32 + q0)      * 66 + eb];
                vi1 += zred[(k * 32 + q0 + 1)  * 66 + eb];
                vf0 += zred[(k * 32 + 8 + q0)  * 66 + eb];
                vf1 += zred[(k * 32 + 9 + q0)  * 66 + eb];
                vg0 += zred[(k * 32 + 16 + q0) * 66 + eb];
                vg1 += zred[(k * 32 + 17 + q0) * 66 + eb];
                vo0 += zred[(k * 32 + 24 + q0) * 66 + eb];
                vo1 += zred[(k * 32 + 25 + q0) * 66 + eb];
            }
            float ig0 = fsigm(vi0), ig1 = fsigm(vi1);
            float fg0 = fsigm(vf0), fg1 = fsigm(vf1);
            float gg0 = ftanh(vg0), gg1 = ftanh(vg1);
            float og0 = fsigm(vo0), og1 = fsigm(vo1);
            cst0 = fg0 * cst0 + ig0 * gg0;
            cst1 = fg1 * cst1 + ig1 * gg1;
            hh0 = og0 * ftanh(cst0);
            hh1 = og1 * ftanh(cst1);

            __stcg(&hdst[(jb * 8 + q0) * 64 + eb],     hh0);
            __stcg(&hdst[(jb * 8 + q0 + 1) * 64 + eb], hh1);
        }

        // arrive early; do DRAM stores + next Z prefetch inside the window
        bar_arrive();

        size_t ho = ((size_t)eb * 1024 + t) * 1024 + dir * 512 + jb * 8 + q0;
        if (ROUND) {
            hout[ho]     = to_tf32(hh0);
            hout[ho + 1] = to_tf32(hh1);
        } else {
            hout[ho]     = hh0;
            hout[ho + 1] = hh1;
        }

        if (s + 1 < TSTEPS) {
            int tn = dir ? (TSTEPS - 2 - s) : (s + 1);
            const float* Zt = Z + ((size_t)tn * 64 + eb) * 2048 + jb * 8 + q0;
            zi2 = *(const float2*)(Zt + 0);
            zf2 = *(const float2*)(Zt + 512);
            zg2 = *(const float2*)(Zt + 1024);
            zo2 = *(const float2*)(Zt + 1536);
            bar_wait(128u * (unsigned)(s + 2));
        }
    }
}

__global__ void reset_bar_kernel() { g_bar = 0u; }

// =====================================================================
extern "C" void kernel_launch(void* const* d_in, const int* in_sizes, int n_in,
                              void* d_out, int out_size)
{
    (void)in_sizes; (void)n_in; (void)out_size;
    const float* x   = (const float*)d_in[0];
    const float* W1f = (const float*)d_in[1];
    const float* U1f = (const float*)d_in[2];
    const float* b1f = (const float*)d_in[3];
    const float* W1b = (const float*)d_in[4];
    const float* U1b = (const float*)d_in[5];
    const float* b1b = (const float*)d_in[6];
    const float* W2f = (const float*)d_in[7];
    const float* U2f = (const float*)d_in[8];
    const float* b2f = (const float*)d_in[9];
    const float* W2b = (const float*)d_in[10];
    const float* U2b = (const float*)d_in[11];
    const float* b2b = (const float*)d_in[12];
    const float* Wd  = (const float*)d_in[13];
    const float* bd  = (const float*)d_in[14];
    float* out = (float*)d_out;

    float *Zf, *Zb, *h1, *h2, *xr;
    float *Wt1f, *Wt1b, *Wt2f, *Wt2b, *Wtd, *WtdLo;
    cudaGetSymbolAddress((void**)&Zf, g_Zf);
    cudaGetSymbolAddress((void**)&Zb, g_Zb);
    cudaGetSymbolAddress((void**)&h1, g_h1);
    cudaGetSymbolAddress((void**)&h2, g_h2);
    cudaGetSymbolAddress((void**)&xr, g_xr);
    cudaGetSymbolAddress((void**)&Wt1f, g_Wt1f);
    cudaGetSymbolAddress((void**)&Wt1b, g_Wt1b);
    cudaGetSymbolAddress((void**)&Wt2f, g_Wt2f);
    cudaGetSymbolAddress((void**)&Wt2b, g_Wt2b);
    cudaGetSymbolAddress((void**)&Wtd, g_Wtd);
    cudaGetSymbolAddress((void**)&WtdLo, g_WtdLo);

    const int GEMM_SMEM = 4 * ABUF * 4;
    cudaFuncSetAttribute(mma_gemm_kernel<0, 0>, cudaFuncAttributeMaxDynamicSharedMemorySize, GEMM_SMEM);
    cudaFuncSetAttribute(mma_gemm_kernel<0, 1>, cudaFuncAttributeMaxDynamicSharedMemorySize, GEMM_SMEM);
    cudaFuncSetAttribute(mma_gemm_kernel<1, 0>, cudaFuncAttributeMaxDynamicSharedMemorySize, GEMM_SMEM);
    cudaFuncSetAttribute(lstm_mma_kernel<0>, cudaFuncAttributeMaxDynamicSharedMemorySize, LSTM_SMEM);
    cudaFuncSetAttribute(lstm_mma_kernel<1>, cudaFuncAttributeMaxDynamicSharedMemorySize, LSTM_SMEM);

    dim3 blk(256);
    dim3 gZ(2048 / 128, 65536 / 128);
    dim3 gO(512 / 128, 65536 / 128);

    // launch 0: fused prep (xr + 4 W transposes + Wd split)
    prep_all_kernel<<<dim3(2048, 6), 256>>>(x, xr, W1f, Wt1f, W1b, Wt1b,
                                            W2f, Wt2f, W2b, Wt2b, Wd, Wtd, WtdLo);

    // launches 1,2: layer-1 input projections
    mma_gemm_kernel<1, 0><<<gZ, blk, GEMM_SMEM>>>(xr, Wt1f, b1f, Zf, 512, 2048);
    mma_gemm_kernel<1, 0><<<gZ, blk, GEMM_SMEM>>>(xr, Wt1b, b1b, Zb, 512, 2048);

    // launches 3,4: barrier reset (+pad so lstm lands at ncu's -s 5 slot)
    reset_bar_kernel<<<1, 1>>>();
    reset_bar_kernel<<<1, 1>>>();

    // launch 5: layer-1 recurrence  <-- ncu profiles this one
    lstm_mma_kernel<1><<<128, 256, LSTM_SMEM>>>(Zf, Zb, U1f, U1b, h1);

    // layer-2 input projections
    mma_gemm_kernel<1, 0><<<gZ, blk, GEMM_SMEM>>>(h1, Wt2f, b2f, Zf, 1024, 2048);
    mma_gemm_kernel<1, 0><<<gZ, blk, GEMM_SMEM>>>(h1, Wt2b, b2b, Zb, 1024, 2048);

    // layer-2 recurrence
    reset_bar_kernel<<<1, 1>>>();
    lstm_mma_kernel<0><<<128, 256, LSTM_SMEM>>>(Zf, Zb, U2f, U2b, h2);

    // dense head, 3-term split: out = (h1+h2)@Wd + bd
    add_split_kernel<<<(16777216 + 255) / 256, 256>>>(h1, h2, Zf, Zb, 16777216);
    mma_gemm_kernel<0, 0><<<gO, blk, GEMM_SMEM>>>(Zf, Wtd,   bd, out, 1024, 512);
    mma_gemm_kernel<0, 1><<<gO, blk, GEMM_SMEM>>>(Zb, Wtd,   bd, out, 1024, 512);
    mma_gemm_kernel<0, 1><<<gO, blk, GEMM_SMEM>>>(Zf, WtdLo, bd, out, 1024, 512);
}

// round 10
// speedup vs baseline: 1.7694x; 1.0589x over previous
#include <cuda_runtime.h>
#include <math.h>
#include <stdint.h>

#define TSTEPS 1024
#define BATCH  64
#define HID    512

// ---------------- scratch (static device allocations; no cudaMalloc) ----------------
__device__ float g_Zf[(size_t)TSTEPS * BATCH * 2048];   // Z fwd [t][b][4H]; later A_hi
__device__ float g_Zb[(size_t)TSTEPS * BATCH * 2048];   // Z bwd [t][b][4H]; later A_lo
__device__ float g_h1[(size_t)BATCH * TSTEPS * 1024];   // layer1 out [b][t][2H] (tf32)
__device__ float g_h2[(size_t)BATCH * TSTEPS * 1024];   // layer2 out [b][t][2H] (fp32)
__device__ float g_xr[(size_t)BATCH * TSTEPS * 512];    // tf32-rounded x
__device__ float g_hst[2][2][HID][BATCH];               // h state [dir][phase][col][b]
__device__ unsigned int g_bar;

// transposed + tf32-rounded weights [N][K]
__device__ float g_Wt1f[2048 * 512];
__device__ float g_Wt1b[2048 * 512];
__device__ float g_Wt2f[2048 * 1024];
__device__ float g_Wt2b[2048 * 1024];
__device__ float g_Wtd [512 * 1024];
__device__ float g_WtdLo[512 * 1024];

__device__ __forceinline__ float to_tf32(float v) {
    float r; asm("cvt.rna.tf32.f32 %0, %1;" : "=f"(r) : "f"(v)); return r;
}
__device__ __forceinline__ uint32_t smem_u32(const void* p) {
    uint32_t a;
    asm("{ .reg .u64 t; cvta.to.shared.u64 t, %1; cvt.u32.u64 %0, t; }" : "=r"(a) : "l"(p));
    return a;
}
__device__ __forceinline__ float fsigm(float x) { return 1.f / (1.f + __expf(-x)); }
__device__ __forceinline__ float ftanh(float x) {
    float e = __expf(2.f * x);
    return 1.f - __fdividef(2.f, e + 1.f);
}
__device__ __forceinline__ void cp16(uint32_t dst, const void* src) {
    asm volatile("cp.async.cg.shared.global [%0], [%1], 16;" :: "r"(dst), "l"(src));
}

// =====================================================================
//  Fused prep kernel: blockIdx.y selects task.
// =====================================================================
__global__ void prep_all_kernel(
    const float* __restrict__ x,   float* __restrict__ xr,
    const float* __restrict__ W1f, float* __restrict__ Wt1f,
    const float* __restrict__ W1b, float* __restrict__ Wt1b,
    const float* __restrict__ W2f, float* __restrict__ Wt2f,
    const float* __restrict__ W2b, float* __restrict__ Wt2b,
    const float* __restrict__ Wd,  float* __restrict__ Wtd, float* __restrict__ WtdLo)
{
    const int task = blockIdx.y;
    if (task == 0) {
        const int n4 = 8388608;
        for (int i = blockIdx.x * 256 + threadIdx.x; i < n4; i += 2048 * 256) {
            float4 v = ((const float4*)x)[i];
            ((float4*)xr)[i] = make_float4(to_tf32(v.x), to_tf32(v.y),
                                           to_tf32(v.z), to_tf32(v.w));
        }
        return;
    }
    const float* W; float* Wt; float* Wlo = nullptr; int K, N;
    switch (task) {
        case 1: W = W1f; Wt = Wt1f; K = 512;  N = 2048; break;
        case 2: W = W1b; Wt = Wt1b; K = 512;  N = 2048; break;
        case 3: W = W2f; Wt = Wt2f; K = 1024; N = 2048; break;
        case 4: W = W2b; Wt = Wt2b; K = 1024; N = 2048; break;
        default: W = Wd; Wt = Wtd; Wlo = WtdLo; K = 1024; N = 512; break;
    }
    const int nkb = K / 32;
    const int total = nkb * (N / 32);
    const int bx = blockIdx.x;
    if (bx >= total) return;
    __shared__ float tile[32][33];
    const int kb = (bx % nkb) * 32, nb = (bx / nkb) * 32;
    const int tx = threadIdx.x & 31, ty = threadIdx.x >> 5;
#pragma unroll
    for (int i = ty; i < 32; i += 8)
        tile[i][tx] = W[(size_t)(kb + i) * N + nb + tx];
    __syncthreads();
#pragma unroll
    for (int i = ty; i < 32; i += 8) {
        float v = tile[tx][i];
        float hi = to_tf32(v);
        Wt[(size_t)(nb + i) * K + kb + tx] = hi;
        if (Wlo) Wlo[(size_t)(nb + i) * K + kb + tx] = to_tf32(v - hi);
    }
}

// A_hi = tf32(h1+h2), A_lo = tf32((h1+h2)-A_hi)
__global__ void add_split_kernel(const float* __restrict__ a, const float* __restrict__ b,
                                 float* __restrict__ ohi, float* __restrict__ olo, int n4)
{
    int i = blockIdx.x * blockDim.x + threadIdx.x;
    if (i < n4) {
        float4 va = ((const float4*)a)[i];
        float4 vb = ((const float4*)b)[i];
        float s0 = va.x + vb.x, s1 = va.y + vb.y, s2 = va.z + vb.z, s3 = va.w + vb.w;
        float h0 = to_tf32(s0), h1v = to_tf32(s1), h2v = to_tf32(s2), h3 = to_tf32(s3);
        ((float4*)ohi)[i] = make_float4(h0, h1v, h2v, h3);
        ((float4*)olo)[i] = make_float4(to_tf32(s0 - h0), to_tf32(s1 - h1v),
                                        to_tf32(s2 - h2v), to_tf32(s3 - h3));
    }
}

// =====================================================================
//  TF32 mma.sync GEMM (validated R4):  C = A @ Bt^T (+bias | +=)
// =====================================================================
#define ABUF 4608   // 128*36 floats per buffer

template <int SCATTER, int ACCUM>
__global__ void __launch_bounds__(256, 2)
mma_gemm_kernel(const float* __restrict__ A, const float* __restrict__ Bt,
                const float* __restrict__ bias, float* __restrict__ C, int K, int N)
{
    extern __shared__ float smf[];
    const int tid = threadIdx.x;
    const int wid = tid >> 5, lane = tid & 31;
    const int warp_m = wid & 1, warp_n = wid >> 1;
    const size_t rowBase = (size_t)blockIdx.y * 128;
    const size_t colBase = (size_t)blockIdx.x * 128;
    const uint32_t smbase = smem_u32(smf);
    const int NS = K >> 5;

    float acc[4][4][4];
#pragma unroll
    for (int mi = 0; mi < 4; ++mi)
#pragma unroll
        for (int ni = 0; ni < 4; ++ni)
#pragma unroll
            for (int r = 0; r < 4; ++r) acc[mi][ni][r] = 0.f;

    auto cp_tile = [&](int s, int p) {
        const int kt = s << 5;
#pragma unroll
        for (int i = 0; i < 4; ++i) {
            int idx = i * 256 + tid;
            int row = idx >> 3, f4 = idx & 7;
            uint32_t da = smbase + (uint32_t)((p * ABUF + row * 36 + f4 * 4) << 2);
            cp16(da, A + (rowBase + row) * K + kt + f4 * 4);
            uint32_t db = smbase + (uint32_t)(((2 * ABUF) + p * ABUF + row * 36 + f4 * 4) << 2);
            cp16(db, Bt + (colBase + row) * K + kt + f4 * 4);
        }
        asm volatile("cp.async.commit_group;");
    };

    cp_tile(0, 0);
    cp_tile(1, 1);

    const int g = lane >> 2, c = lane & 3;
    const int ar0 = warp_m * 64 + g;
    const int bn0 = warp_n * 32 + g;

    for (int s = 0; s < NS; ++s) {
        const int p = s & 1;
        if (s + 1 < NS) asm volatile("cp.async.wait_group 1;");
        else            asm volatile("cp.async.wait_group 0;");
        __syncthreads();

        const float* Ab = smf + p * ABUF;
        const float* Bb = smf + 2 * ABUF + p * ABUF;

#pragma unroll
        for (int k8 = 0; k8 < 4; ++k8) {
            const int kc = k8 * 8 + c;
            uint32_t a[4][4], b[4][2];
#pragma unroll
            for (int mi = 0; mi < 4; ++mi) {
                const float* base = Ab + (ar0 + mi * 16) * 36 + kc;
                a[mi][0] = __float_as_uint(base[0]);
                a[mi][1] = __float_as_uint(base[8 * 36]);
                a[mi][2] = __float_as_uint(base[4]);
                a[mi][3] = __float_as_uint(base[8 * 36 + 4]);
            }
#pragma unroll
            for (int ni = 0; ni < 4; ++ni) {
                const float* base = Bb + (bn0 + ni * 8) * 36 + kc;
                b[ni][0] = __float_as_uint(base[0]);
                b[ni][1] = __float_as_uint(base[4]);
            }
#pragma unroll
            for (int mi = 0; mi < 4; ++mi)
#pragma unroll
                for (int ni = 0; ni < 4; ++ni)
                    asm volatile(
                        "mma.sync.aligned.m16n8k8.row.col.f32.tf32.tf32.f32 "
                        "{%0,%1,%2,%3}, {%4,%5,%6,%7}, {%8,%9}, {%0,%1,%2,%3};"
                        : "+f"(acc[mi][ni][0]), "+f"(acc[mi][ni][1]),
                          "+f"(acc[mi][ni][2]), "+f"(acc[mi][ni][3])
                        : "r"(a[mi][0]), "r"(a[mi][1]), "r"(a[mi][2]), "r"(a[mi][3]),
                          "r"(b[ni][0]), "r"(b[ni][1]));
        }
        __syncthreads();
        if (s + 2 < NS) cp_tile(s + 2, p);
    }

    const int c2 = (lane & 3) * 2;
#pragma unroll
    for (int mi = 0; mi < 4; ++mi) {
        size_t r0 = rowBase + warp_m * 64 + mi * 16 + g;
        size_t r8 = r0 + 8;
        size_t off0, off8;
        if (SCATTER) {
            off0 = (((r0 & 1023) << 6) + (r0 >> 10)) * (size_t)N;
            off8 = (((r8 & 1023) << 6) + (r8 >> 10)) * (size_t)N;
        } else {
            off0 = r0 * (size_t)N;
            off8 = r8 * (size_t)N;
        }
#pragma unroll
        for (int ni = 0; ni < 4; ++ni) {
            size_t col = colBase + warp_n * 32 + ni * 8 + c2;
            float2 v0, v1;
            if (ACCUM) {
                float2 o0 = *(const float2*)&C[off0 + col];
                float2 o1 = *(const float2*)&C[off8 + col];
                v0 = make_float2(acc[mi][ni][0] + o0.x, acc[mi][ni][1] + o0.y);
                v1 = make_float2(acc[mi][ni][2] + o1.x, acc[mi][ni][3] + o1.y);
            } else {
                float2 bv = *(const float2*)&bias[col];
                v0 = make_float2(acc[mi][ni][0] + bv.x, acc[mi][ni][1] + bv.y);
                v1 = make_float2(acc[mi][ni][2] + bv.x, acc[mi][ni][3] + bv.y);
            }
            *(float2*)&C[off0 + col] = v0;
            *(float2*)&C[off8 + col] = v1;
        }
    }
}

// =====================================================================
//  Persistent bidirectional LSTM layer — tensor-core recurrence.
//  R10: cp.async staging (no reg round-trip) + pair-scoped named barrier.
// =====================================================================
__device__ __forceinline__ void bar_arrive()
{
    __threadfence();
    __syncthreads();
    if (threadIdx.x == 0) atomicAdd(&g_bar, 1u);
}
__device__ __forceinline__ void bar_wait(unsigned int target)
{
    if (threadIdx.x == 0)
        while (*(volatile unsigned int*)&g_bar < target) { }
    __syncthreads();
}

#define LSTM_SMEM ((36864 + 4 * 32 * 66) * 4)

template <int ROUND>
__global__ void __launch_bounds__(256, 1)
lstm_mma_kernel(const float* __restrict__ Zf, const float* __restrict__ Zb,
                const float* __restrict__ Uf, const float* __restrict__ Ub,
                float* __restrict__ hout)
{
    extern __shared__ float sm[];
    float* hs   = sm;           // [4 ks][128 k][72]  (pad-72)
    float* zred = sm + 36864;   // [4 ks][32 l][66]

    const int tid = threadIdx.x;
    const int w = tid >> 5, lane = tid & 31;
    const int g = lane >> 2, c = lane & 3;
    const int ks = w >> 1, mg = w & 1;
    const int dir = blockIdx.x >> 6;
    const int jb  = blockIdx.x & 63;
    const float* U = dir ? Ub : Uf;
    const float* Z = dir ? Zb : Zf;
    float* hst0 = &g_hst[dir][0][0][0];
    float* hst1 = &g_hst[dir][1][0][0];

    // ---- one-time: U A-fragments (split tf32 hi+lo), registers ----
    float uhi[16][4], ulo[16][4];
    {
        const int l0 = mg * 16 + g, l1 = l0 + 8;
        const int gc0 = (l0 >> 3) * 512 + jb * 8 + (l0 & 7);
        const int gc1 = (l1 >> 3) * 512 + jb * 8 + (l1 & 7);
#pragma unroll
        for (int kk = 0; kk < 16; ++kk) {
            int k = ks * 128 + kk * 8;
            float v0 = U[(size_t)(k + c) * 2048 + gc0];
            float v1 = U[(size_t)(k + c) * 2048 + gc1];
            float v2 = U[(size_t)(k + c + 4) * 2048 + gc0];
            float v3 = U[(size_t)(k + c + 4) * 2048 + gc1];
            uhi[kk][0] = to_tf32(v0); ulo[kk][0] = v0 - uhi[kk][0];
            uhi[kk][1] = to_tf32(v1); ulo[kk][1] = v1 - uhi[kk][1];
            uhi[kk][2] = to_tf32(v2); ulo[kk][2] = v2 - uhi[kk][2];
            uhi[kk][3] = to_tf32(v3); ulo[kk][3] = v3 - uhi[kk][3];
        }
    }

    // zero own cols of phase-0 state
    for (int i = tid; i < 512; i += 256) hst0[jb * 8 * 64 + i] = 0.f;
    bar_arrive();
    bar_wait(128u);

    const int eb = tid >> 2;
    const int q0 = (tid & 3) * 2;
    float cst0 = 0.f, cst1 = 0.f;
    const int pt = tid & 63;
    float* hsP = hs + ks * 9216;
    const uint32_t hsPb = smem_u32(hsP);

    // prologue Z prefetch for s=0
    float2 zi2, zf2, zg2, zo2;
    {
        int t0 = dir ? (TSTEPS - 1) : 0;
        const float* Zt = Z + ((size_t)t0 * 64 + eb) * 2048 + jb * 8 + q0;
        zi2 = *(const float2*)(Zt + 0);
        zf2 = *(const float2*)(Zt + 512);
        zg2 = *(const float2*)(Zt + 1024);
        zo2 = *(const float2*)(Zt + 1536);
    }

    for (int s = 0; s < TSTEPS; ++s) {
        const int t = dir ? (TSTEPS - 1 - s) : s;
        const float* hsrc = (s & 1) ? hst1 : hst0;
        float* hdst = (s & 1) ? hst0 : hst1;

        // ---- stage pair's K-slice via cp.async: [col][b] -> smem [k][72] ----
        {
            const float4* src = (const float4*)(hsrc + ks * 8192);
#pragma unroll
            for (int i = 0; i < 32; ++i) {
                int idx = i * 64 + pt;          // 0..2047 float4
                int kl = idx >> 4, q4 = idx & 15;
                cp16(hsPb + (uint32_t)((kl * 72 + q4 * 4) << 2), src + idx);
            }
            asm volatile("cp.async.commit_group;");
            asm volatile("cp.async.wait_group 0;");
        }
        // pair-scoped sync: only the 64 threads of this warp-pair
        asm volatile("bar.sync %0, %1;" :: "r"(1 + ks), "r"(64) : "memory");

        // ---- MMA: z[l=mg*16..+16][b=0..63] over k in [ks*128,+128) ----
        float acc[8][4];
#pragma unroll
        for (int nt = 0; nt < 8; ++nt)
#pragma unroll
            for (int r = 0; r < 4; ++r) acc[nt][r] = 0.f;

#pragma unroll
        for (int kk = 0; kk < 16; ++kk) {
            uint32_t ah0 = __float_as_uint(uhi[kk][0]), ah1 = __float_as_uint(uhi[kk][1]);
            uint32_t ah2 = __float_as_uint(uhi[kk][2]), ah3 = __float_as_uint(uhi[kk][3]);
            uint32_t al0 = __float_as_uint(ulo[kk][0]), al1 = __float_as_uint(ulo[kk][1]);
            uint32_t al2 = __float_as_uint(ulo[kk][2]), al3 = __float_as_uint(ulo[kk][3]);
            const float* rowA = hsP + (kk * 8 + c) * 72;
            const float* rowB = rowA + 4 * 72;
#pragma unroll
            for (int nt = 0; nt < 8; ++nt) {
                float b0f = rowA[nt * 8 + g];
                float b1f = rowB[nt * 8 + g];
                float bh0 = to_tf32(b0f), bh1 = to_tf32(b1f);
                float bl0 = b0f - bh0,    bl1 = b1f - bh1;
                asm volatile(
                    "mma.sync.aligned.m16n8k8.row.col.f32.tf32.tf32.f32 "
                    "{%0,%1,%2,%3}, {%4,%5,%6,%7}, {%8,%9}, {%0,%1,%2,%3};"
                    : "+f"(acc[nt][0]), "+f"(acc[nt][1]), "+f"(acc[nt][2]), "+f"(acc[nt][3])
                    : "r"(ah0), "r"(ah1), "r"(ah2), "r"(ah3),
                      "r"(__float_as_uint(bh0)), "r"(__float_as_uint(bh1)));
                asm volatile(
                    "mma.sync.aligned.m16n8k8.row.col.f32.tf32.tf32.f32 "
                    "{%0,%1,%2,%3}, {%4,%5,%6,%7}, {%8,%9}, {%0,%1,%2,%3};"
                    : "+f"(acc[nt][0]), "+f"(acc[nt][1]), "+f"(acc[nt][2]), "+f"(acc[nt][3])
                    : "r"(ah0), "r"(ah1), "r"(ah2), "r"(ah3),
                      "r"(__float_as_uint(bl0)), "r"(__float_as_uint(bl1)));
                asm volatile(
                    "mma.sync.aligned.m16n8k8.row.col.f32.tf32.tf32.f32 "
                    "{%0,%1,%2,%3}, {%4,%5,%6,%7}, {%8,%9}, {%0,%1,%2,%3};"
                    : "+f"(acc[nt][0]), "+f"(acc[nt][1]), "+f"(acc[nt][2]), "+f"(acc[nt][3])
                    : "r"(al0), "r"(al1), "r"(al2), "r"(al3),
                      "r"(__float_as_uint(bh0)), "r"(__float_as_uint(bh1)));
            }
        }

        // ---- store partials: zred[ks][l][b] ----
#pragma unroll
        for (int nt = 0; nt < 8; ++nt) {
            int l0 = mg * 16 + g;
            int n0 = nt * 8 + c * 2;
            *(float2*)&zred[(ks * 32 + l0) * 66 + n0]     = make_float2(acc[nt][0], acc[nt][1]);
            *(float2*)&zred[(ks * 32 + l0 + 8) * 66 + n0] = make_float2(acc[nt][2], acc[nt][3]);
        }
        __syncthreads();

        // ---- gate epilogue ----
        float hh0, hh1;
        {
            float vi0 = zi2.x, vi1 = zi2.y, vf0 = zf2.x, vf1 = zf2.y;
            float vg0 = zg2.x, vg1 = zg2.y, vo0 = zo2.x, vo1 = zo2.y;
#pragma unroll
            for (int k = 0; k < 4; ++k) {
                vi0 += zred[(k * 32 + q0)      * 66 + eb];
                vi1 += zred[(k * 32 + q0 + 1)  * 66 + eb];
                vf0 += zred[(k * 32 + 8 + q0)  * 66 + eb];
                vf1 += zred[(k * 32 + 9 + q0)  * 66 + eb];
                vg0 += zred[(k * 32 + 16 + q0) * 66 + eb];
                vg1 += zred[(k * 32 + 17 + q0) * 66 + eb];
                vo0 += zred[(k * 32 + 24 + q0) * 66 + eb];
                vo1 += zred[(k * 32 + 25 + q0) * 66 + eb];
            }
            float ig0 = fsigm(vi0), ig1 = fsigm(vi1);
            float fg0 = fsigm(vf0), fg1 = fsigm(vf1);
            float gg0 = ftanh(vg0), gg1 = ftanh(vg1);
            float og0 = fsigm(vo0), og1 = fsigm(vo1);
            cst0 = fg0 * cst0 + ig0 * gg0;
            cst1 = fg1 * cst1 + ig1 * gg1;
            hh0 = og0 * ftanh(cst0);
            hh1 = og1 * ftanh(cst1);

            __stcg(&hdst[(jb * 8 + q0) * 64 + eb],     hh0);
            __stcg(&hdst[(jb * 8 + q0 + 1) * 64 + eb], hh1);
        }

        bar_arrive();

        size_t ho = ((size_t)eb * 1024 + t) * 1024 + dir * 512 + jb * 8 + q0;
        if (ROUND) {
            hout[ho]     = to_tf32(hh0);
            hout[ho + 1] = to_tf32(hh1);
        } else {
            hout[ho]     = hh0;
            hout[ho + 1] = hh1;
        }

        if (s + 1 < TSTEPS) {
            int tn = dir ? (TSTEPS - 2 - s) : (s + 1);
            const float* Zt = Z + ((size_t)tn * 64 + eb) * 2048 + jb * 8 + q0;
            zi2 = *(const float2*)(Zt + 0);
            zf2 = *(const float2*)(Zt + 512);
            zg2 = *(const float2*)(Zt + 1024);
            zo2 = *(const float2*)(Zt + 1536);
            bar_wait(128u * (unsigned)(s + 2));
        }
    }
}

__global__ void reset_bar_kernel() { g_bar = 0u; }

// =====================================================================
extern "C" void kernel_launch(void* const* d_in, const int* in_sizes, int n_in,
                              void* d_out, int out_size)
{
    (void)in_sizes; (void)n_in; (void)out_size;
    const float* x   = (const float*)d_in[0];
    const float* W1f = (const float*)d_in[1];
    const float* U1f = (const float*)d_in[2];
    const float* b1f = (const float*)d_in[3];
    const float* W1b = (const float*)d_in[4];
    const float* U1b = (const float*)d_in[5];
    const float* b1b = (const float*)d_in[6];
    const float* W2f = (const float*)d_in[7];
    const float* U2f = (const float*)d_in[8];
    const float* b2f = (const float*)d_in[9];
    const float* W2b = (const float*)d_in[10];
    const float* U2b = (const float*)d_in[11];
    const float* b2b = (const float*)d_in[12];
    const float* Wd  = (const float*)d_in[13];
    const float* bd  = (const float*)d_in[14];
    float* out = (float*)d_out;

    float *Zf, *Zb, *h1, *h2, *xr;
    float *Wt1f, *Wt1b, *Wt2f, *Wt2b, *Wtd, *WtdLo;
    cudaGetSymbolAddress((void**)&Zf, g_Zf);
    cudaGetSymbolAddress((void**)&Zb, g_Zb);
    cudaGetSymbolAddress((void**)&h1, g_h1);
    cudaGetSymbolAddress((void**)&h2, g_h2);
    cudaGetSymbolAddress((void**)&xr, g_xr);
    cudaGetSymbolAddress((void**)&Wt1f, g_Wt1f);
    cudaGetSymbolAddress((void**)&Wt1b, g_Wt1b);
    cudaGetSymbolAddress((void**)&Wt2f, g_Wt2f);
    cudaGetSymbolAddress((void**)&Wt2b, g_Wt2b);
    cudaGetSymbolAddress((void**)&Wtd, g_Wtd);
    cudaGetSymbolAddress((void**)&WtdLo, g_WtdLo);

    const int GEMM_SMEM = 4 * ABUF * 4;
    cudaFuncSetAttribute(mma_gemm_kernel<0, 0>, cudaFuncAttributeMaxDynamicSharedMemorySize, GEMM_SMEM);
    cudaFuncSetAttribute(mma_gemm_kernel<0, 1>, cudaFuncAttributeMaxDynamicSharedMemorySize, GEMM_SMEM);
    cudaFuncSetAttribute(mma_gemm_kernel<1, 0>, cudaFuncAttributeMaxDynamicSharedMemorySize, GEMM_SMEM);
    cudaFuncSetAttribute(lstm_mma_kernel<0>, cudaFuncAttributeMaxDynamicSharedMemorySize, LSTM_SMEM);
    cudaFuncSetAttribute(lstm_mma_kernel<1>, cudaFuncAttributeMaxDynamicSharedMemorySize, LSTM_SMEM);

    dim3 blk(256);
    dim3 gZ(2048 / 128, 65536 / 128);
    dim3 gO(512 / 128, 65536 / 128);

    // launches 0-3: prep, 2 gemms, barrier reset
    prep_all_kernel<<<dim3(2048, 6), 256>>>(x, xr, W1f, Wt1f, W1b, Wt1b,
                                            W2f, Wt2f, W2b, Wt2b, Wd, Wtd, WtdLo);
    mma_gemm_kernel<1, 0><<<gZ, blk, GEMM_SMEM>>>(xr, Wt1f, b1f, Zf, 512, 2048);
    mma_gemm_kernel<1, 0><<<gZ, blk, GEMM_SMEM>>>(xr, Wt1b, b1b, Zb, 512, 2048);
    reset_bar_kernel<<<1, 1>>>();

    // launch 4 (ncu -s 5 captures the 5th launch == this one): layer-1 recurrence
    lstm_mma_kernel<1><<<128, 256, LSTM_SMEM>>>(Zf, Zb, U1f, U1b, h1);

    // layer-2 input projections
    mma_gemm_kernel<1, 0><<<gZ, blk, GEMM_SMEM>>>(h1, Wt2f, b2f, Zf, 1024, 2048);
    mma_gemm_kernel<1, 0><<<gZ, blk, GEMM_SMEM>>>(h1, Wt2b, b2b, Zb, 1024, 2048);

    // layer-2 recurrence
    reset_bar_kernel<<<1, 1>>>();
    lstm_mma_kernel<0><<<128, 256, LSTM_SMEM>>>(Zf, Zb, U2f, U2b, h2);

    // dense head, 3-term split: out = (h1+h2)@Wd + bd
    add_split_kernel<<<(16777216 + 255) / 256, 256>>>(h1, h2, Zf, Zb, 16777216);
    mma_gemm_kernel<0, 0><<<gO, blk, GEMM_SMEM>>>(Zf, Wtd,   bd, out, 1024, 512);
    mma_gemm_kernel<0, 1><<<gO, blk, GEMM_SMEM>>>(Zb, Wtd,   bd, out, 1024, 512);
    mma_gemm_kernel<0, 1><<<gO, blk, GEMM_SMEM>>>(Zf, WtdLo, bd, out, 1024, 512);
}

// round 11
// speedup vs baseline: 2.0513x; 1.1593x over previous
#include <cuda_runtime.h>
#include <math.h>
#include <stdint.h>

#define TSTEPS 1024
#define BATCH  64
#define HID    512

// ---------------- scratch (static device allocations; no cudaMalloc) ----------------
__device__ float g_Zf[(size_t)TSTEPS * BATCH * 2048];   // Z fwd [t][b][4H]; later A_hi
__device__ float g_Zb[(size_t)TSTEPS * BATCH * 2048];   // Z bwd [t][b][4H]; later A_lo
__device__ float g_h1[(size_t)BATCH * TSTEPS * 1024];   // layer1 out [b][t][2H] (tf32)
__device__ float g_h2[(size_t)BATCH * TSTEPS * 1024];   // layer2 out [b][t][2H] (fp32)
__device__ float g_xr[(size_t)BATCH * TSTEPS * 512];    // tf32-rounded x
__device__ float g_hst[2][2][HID][BATCH];               // h state [dir][phase][col][b]
__device__ unsigned int g_bar2[64];                     // per-dir barrier counters ([0],[32])

// transposed + tf32-rounded weights [N][K]
__device__ float g_Wt1f[2048 * 512];
__device__ float g_Wt1b[2048 * 512];
__device__ float g_Wt2f[2048 * 1024];
__device__ float g_Wt2b[2048 * 1024];
__device__ float g_Wtd [512 * 1024];
__device__ float g_WtdLo[512 * 1024];

__device__ __forceinline__ float to_tf32(float v) {
    float r; asm("cvt.rna.tf32.f32 %0, %1;" : "=f"(r) : "f"(v)); return r;
}
__device__ __forceinline__ uint32_t smem_u32(const void* p) {
    uint32_t a;
    asm("{ .reg .u64 t; cvta.to.shared.u64 t, %1; cvt.u32.u64 %0, t; }" : "=r"(a) : "l"(p));
    return a;
}
__device__ __forceinline__ float fsigm(float x) { return 1.f / (1.f + __expf(-x)); }
__device__ __forceinline__ float ftanh(float x) {
    float e = __expf(2.f * x);
    return 1.f - __fdividef(2.f, e + 1.f);
}
__device__ __forceinline__ void cp16(uint32_t dst, const void* src) {
    asm volatile("cp.async.cg.shared.global [%0], [%1], 16;" :: "r"(dst), "l"(src));
}

// =====================================================================
//  Fused prep kernel: blockIdx.y selects task.
// =====================================================================
__global__ void prep_all_kernel(
    const float* __restrict__ x,   float* __restrict__ xr,
    const float* __restrict__ W1f, float* __restrict__ Wt1f,
    const float* __restrict__ W1b, float* __restrict__ Wt1b,
    const float* __restrict__ W2f, float* __restrict__ Wt2f,
    const float* __restrict__ W2b, float* __restrict__ Wt2b,
    const float* __restrict__ Wd,  float* __restrict__ Wtd, float* __restrict__ WtdLo)
{
    const int task = blockIdx.y;
    if (task == 0) {
        const int n4 = 8388608;
        for (int i = blockIdx.x * 256 + threadIdx.x; i < n4; i += 2048 * 256) {
            float4 v = ((const float4*)x)[i];
            ((float4*)xr)[i] = make_float4(to_tf32(v.x), to_tf32(v.y),
                                           to_tf32(v.z), to_tf32(v.w));
        }
        return;
    }
    const float* W; float* Wt; float* Wlo = nullptr; int K, N;
    switch (task) {
        case 1: W = W1f; Wt = Wt1f; K = 512;  N = 2048; break;
        case 2: W = W1b; Wt = Wt1b; K = 512;  N = 2048; break;
        case 3: W = W2f; Wt = Wt2f; K = 1024; N = 2048; break;
        case 4: W = W2b; Wt = Wt2b; K = 1024; N = 2048; break;
        default: W = Wd; Wt = Wtd; Wlo = WtdLo; K = 1024; N = 512; break;
    }
    const int nkb = K / 32;
    const int total = nkb * (N / 32);
    const int bx = blockIdx.x;
    if (bx >= total) return;
    __shared__ float tile[32][33];
    const int kb = (bx % nkb) * 32, nb = (bx / nkb) * 32;
    const int tx = threadIdx.x & 31, ty = threadIdx.x >> 5;
#pragma unroll
    for (int i = ty; i < 32; i += 8)
        tile[i][tx] = W[(size_t)(kb + i) * N + nb + tx];
    __syncthreads();
#pragma unroll
    for (int i = ty; i < 32; i += 8) {
        float v = tile[tx][i];
        float hi = to_tf32(v);
        Wt[(size_t)(nb + i) * K + kb + tx] = hi;
        if (Wlo) Wlo[(size_t)(nb + i) * K + kb + tx] = to_tf32(v - hi);
    }
}

// A_hi = tf32(h1+h2), A_lo = tf32((h1+h2)-A_hi)
__global__ void add_split_kernel(const float* __restrict__ a, const float* __restrict__ b,
                                 float* __restrict__ ohi, float* __restrict__ olo, int n4)
{
    int i = blockIdx.x * blockDim.x + threadIdx.x;
    if (i < n4) {
        float4 va = ((const float4*)a)[i];
        float4 vb = ((const float4*)b)[i];
        float s0 = va.x + vb.x, s1 = va.y + vb.y, s2 = va.z + vb.z, s3 = va.w + vb.w;
        float h0 = to_tf32(s0), h1v = to_tf32(s1), h2v = to_tf32(s2), h3 = to_tf32(s3);
        ((float4*)ohi)[i] = make_float4(h0, h1v, h2v, h3);
        ((float4*)olo)[i] = make_float4(to_tf32(s0 - h0), to_tf32(s1 - h1v),
                                        to_tf32(s2 - h2v), to_tf32(s3 - h3));
    }
}

// =====================================================================
//  TF32 mma.sync GEMM (validated R4):  C = A @ Bt^T (+bias | +=)
// =====================================================================
#define ABUF 4608   // 128*36 floats per buffer

template <int SCATTER, int ACCUM>
__global__ void __launch_bounds__(256, 2)
mma_gemm_kernel(const float* __restrict__ A, const float* __restrict__ Bt,
                const float* __restrict__ bias, float* __restrict__ C, int K, int N)
{
    extern __shared__ float smf[];
    const int tid = threadIdx.x;
    const int wid = tid >> 5, lane = tid & 31;
    const int warp_m = wid & 1, warp_n = wid >> 1;
    const size_t rowBase = (size_t)blockIdx.y * 128;
    const size_t colBase = (size_t)blockIdx.x * 128;
    const uint32_t smbase = smem_u32(smf);
    const int NS = K >> 5;

    float acc[4][4][4];
#pragma unroll
    for (int mi = 0; mi < 4; ++mi)
#pragma unroll
        for (int ni = 0; ni < 4; ++ni)
#pragma unroll
            for (int r = 0; r < 4; ++r) acc[mi][ni][r] = 0.f;

    auto cp_tile = [&](int s, int p) {
        const int kt = s << 5;
#pragma unroll
        for (int i = 0; i < 4; ++i) {
            int idx = i * 256 + tid;
            int row = idx >> 3, f4 = idx & 7;
            uint32_t da = smbase + (uint32_t)((p * ABUF + row * 36 + f4 * 4) << 2);
            cp16(da, A + (rowBase + row) * K + kt + f4 * 4);
            uint32_t db = smbase + (uint32_t)(((2 * ABUF) + p * ABUF + row * 36 + f4 * 4) << 2);
            cp16(db, Bt + (colBase + row) * K + kt + f4 * 4);
        }
        asm volatile("cp.async.commit_group;");
    };

    cp_tile(0, 0);
    cp_tile(1, 1);

    const int g = lane >> 2, c = lane & 3;
    const int ar0 = warp_m * 64 + g;
    const int bn0 = warp_n * 32 + g;

    for (int s = 0; s < NS; ++s) {
        const int p = s & 1;
        if (s + 1 < NS) asm volatile("cp.async.wait_group 1;");
        else            asm volatile("cp.async.wait_group 0;");
        __syncthreads();

        const float* Ab = smf + p * ABUF;
        const float* Bb = smf + 2 * ABUF + p * ABUF;

#pragma unroll
        for (int k8 = 0; k8 < 4; ++k8) {
            const int kc = k8 * 8 + c;
            uint32_t a[4][4], b[4][2];
#pragma unroll
            for (int mi = 0; mi < 4; ++mi) {
                const float* base = Ab + (ar0 + mi * 16) * 36 + kc;
                a[mi][0] = __float_as_uint(base[0]);
                a[mi][1] = __float_as_uint(base[8 * 36]);
                a[mi][2] = __float_as_uint(base[4]);
                a[mi][3] = __float_as_uint(base[8 * 36 + 4]);
            }
#pragma unroll
            for (int ni = 0; ni < 4; ++ni) {
                const float* base = Bb + (bn0 + ni * 8) * 36 + kc;
                b[ni][0] = __float_as_uint(base[0]);
                b[ni][1] = __float_as_uint(base[4]);
            }
#pragma unroll
            for (int mi = 0; mi < 4; ++mi)
#pragma unroll
                for (int ni = 0; ni < 4; ++ni)
                    asm volatile(
                        "mma.sync.aligned.m16n8k8.row.col.f32.tf32.tf32.f32 "
                        "{%0,%1,%2,%3}, {%4,%5,%6,%7}, {%8,%9}, {%0,%1,%2,%3};"
                        : "+f"(acc[mi][ni][0]), "+f"(acc[mi][ni][1]),
                          "+f"(acc[mi][ni][2]), "+f"(acc[mi][ni][3])
                        : "r"(a[mi][0]), "r"(a[mi][1]), "r"(a[mi][2]), "r"(a[mi][3]),
                          "r"(b[ni][0]), "r"(b[ni][1]));
        }
        __syncthreads();
        if (s + 2 < NS) cp_tile(s + 2, p);
    }

    const int c2 = (lane & 3) * 2;
#pragma unroll
    for (int mi = 0; mi < 4; ++mi) {
        size_t r0 = rowBase + warp_m * 64 + mi * 16 + g;
        size_t r8 = r0 + 8;
        size_t off0, off8;
        if (SCATTER) {
            off0 = (((r0 & 1023) << 6) + (r0 >> 10)) * (size_t)N;
            off8 = (((r8 & 1023) << 6) + (r8 >> 10)) * (size_t)N;
        } else {
            off0 = r0 * (size_t)N;
            off8 = r8 * (size_t)N;
        }
#pragma unroll
        for (int ni = 0; ni < 4; ++ni) {
            size_t col = colBase + warp_n * 32 + ni * 8 + c2;
            float2 v0, v1;
            if (ACCUM) {
                float2 o0 = *(const float2*)&C[off0 + col];
                float2 o1 = *(const float2*)&C[off8 + col];
                v0 = make_float2(acc[mi][ni][0] + o0.x, acc[mi][ni][1] + o0.y);
                v1 = make_float2(acc[mi][ni][2] + o1.x, acc[mi][ni][3] + o1.y);
            } else {
                float2 bv = *(const float2*)&bias[col];
                v0 = make_float2(acc[mi][ni][0] + bv.x, acc[mi][ni][1] + bv.y);
                v1 = make_float2(acc[mi][ni][2] + bv.x, acc[mi][ni][3] + bv.y);
            }
            *(float2*)&C[off0 + col] = v0;
            *(float2*)&C[off8 + col] = v1;
        }
    }
}

// =====================================================================
//  Persistent bidirectional LSTM layer — tensor-core recurrence.
//  R11: 2-MMA compensated product (U tf32-rounded; h residual kept) +
//  per-direction grid barriers (64-CTA population each).
// =====================================================================
__device__ __forceinline__ void bar_arrive(int dir)
{
    __threadfence();
    __syncthreads();
    if (threadIdx.x == 0) atomicAdd(&g_bar2[dir * 32], 1u);
}
__device__ __forceinline__ void bar_wait(int dir, unsigned int target)
{
    if (threadIdx.x == 0)
        while (*(volatile unsigned int*)&g_bar2[dir * 32] < target) { }
    __syncthreads();
}

#define LSTM_SMEM ((36864 + 4 * 32 * 66) * 4)

template <int ROUND>
__global__ void __launch_bounds__(256, 1)
lstm_mma_kernel(const float* __restrict__ Zf, const float* __restrict__ Zb,
                const float* __restrict__ Uf, const float* __restrict__ Ub,
                float* __restrict__ hout)
{
    extern __shared__ float sm[];
    float* hs   = sm;           // [4 ks][128 k][72]  (pad-72)
    float* zred = sm + 36864;   // [4 ks][32 l][66]

    const int tid = threadIdx.x;
    const int w = tid >> 5, lane = tid & 31;
    const int g = lane >> 2, c = lane & 3;
    const int ks = w >> 1, mg = w & 1;
    const int dir = blockIdx.x >> 6;
    const int jb  = blockIdx.x & 63;
    const float* U = dir ? Ub : Uf;
    const float* Z = dir ? Zb : Zf;
    float* hst0 = &g_hst[dir][0][0][0];
    float* hst1 = &g_hst[dir][1][0][0];

    // ---- one-time: U A-fragments (tf32-rounded), registers ----
    float uhi[16][4];
    {
        const int l0 = mg * 16 + g, l1 = l0 + 8;
        const int gc0 = (l0 >> 3) * 512 + jb * 8 + (l0 & 7);
        const int gc1 = (l1 >> 3) * 512 + jb * 8 + (l1 & 7);
#pragma unroll
        for (int kk = 0; kk < 16; ++kk) {
            int k = ks * 128 + kk * 8;
            uhi[kk][0] = to_tf32(U[(size_t)(k + c) * 2048 + gc0]);
            uhi[kk][1] = to_tf32(U[(size_t)(k + c) * 2048 + gc1]);
            uhi[kk][2] = to_tf32(U[(size_t)(k + c + 4) * 2048 + gc0]);
            uhi[kk][3] = to_tf32(U[(size_t)(k + c + 4) * 2048 + gc1]);
        }
    }

    // zero own cols of phase-0 state
    for (int i = tid; i < 512; i += 256) hst0[jb * 8 * 64 + i] = 0.f;
    bar_arrive(dir);
    bar_wait(dir, 64u);

    const int eb = tid >> 2;
    const int q0 = (tid & 3) * 2;
    float cst0 = 0.f, cst1 = 0.f;
    const int pt = tid & 63;
    float* hsP = hs + ks * 9216;
    const uint32_t hsPb = smem_u32(hsP);

    // prologue Z prefetch for s=0
    float2 zi2, zf2, zg2, zo2;
    {
        int t0 = dir ? (TSTEPS - 1) : 0;
        const float* Zt = Z + ((size_t)t0 * 64 + eb) * 2048 + jb * 8 + q0;
        zi2 = *(const float2*)(Zt + 0);
        zf2 = *(const float2*)(Zt + 512);
        zg2 = *(const float2*)(Zt + 1024);
        zo2 = *(const float2*)(Zt + 1536);
    }

    for (int s = 0; s < TSTEPS; ++s) {
        const int t = dir ? (TSTEPS - 1 - s) : s;
        const float* hsrc = (s & 1) ? hst1 : hst0;
        float* hdst = (s & 1) ? hst0 : hst1;

        // ---- stage pair's K-slice via cp.async: [col][b] -> smem [k][72] ----
        {
            const float4* src = (const float4*)(hsrc + ks * 8192);
#pragma unroll
            for (int i = 0; i < 32; ++i) {
                int idx = i * 64 + pt;
                int kl = idx >> 4, q4 = idx & 15;
                cp16(hsPb + (uint32_t)((kl * 72 + q4 * 4) << 2), src + idx);
            }
            asm volatile("cp.async.commit_group;");
            asm volatile("cp.async.wait_group 0;");
        }
        asm volatile("bar.sync %0, %1;" :: "r"(1 + ks), "r"(64) : "memory");

        // ---- MMA: z[l=mg*16..+16][b=0..63] over k in [ks*128,+128) ----
        float acc[8][4];
#pragma unroll
        for (int nt = 0; nt < 8; ++nt)
#pragma unroll
            for (int r = 0; r < 4; ++r) acc[nt][r] = 0.f;

#pragma unroll
        for (int kk = 0; kk < 16; ++kk) {
            uint32_t ah0 = __float_as_uint(uhi[kk][0]), ah1 = __float_as_uint(uhi[kk][1]);
            uint32_t ah2 = __float_as_uint(uhi[kk][2]), ah3 = __float_as_uint(uhi[kk][3]);
            const float* rowA = hsP + (kk * 8 + c) * 72;
            const float* rowB = rowA + 4 * 72;
#pragma unroll
            for (int nt = 0; nt < 8; ++nt) {
                float b0f = rowA[nt * 8 + g];
                float b1f = rowB[nt * 8 + g];
                float bh0 = to_tf32(b0f), bh1 = to_tf32(b1f);
                float bl0 = b0f - bh0,    bl1 = b1f - bh1;
                asm volatile(
                    "mma.sync.aligned.m16n8k8.row.col.f32.tf32.tf32.f32 "
                    "{%0,%1,%2,%3}, {%4,%5,%6,%7}, {%8,%9}, {%0,%1,%2,%3};"
                    : "+f"(acc[nt][0]), "+f"(acc[nt][1]), "+f"(acc[nt][2]), "+f"(acc[nt][3])
                    : "r"(ah0), "r"(ah1), "r"(ah2), "r"(ah3),
                      "r"(__float_as_uint(bh0)), "r"(__float_as_uint(bh1)));
                asm volatile(
                    "mma.sync.aligned.m16n8k8.row.col.f32.tf32.tf32.f32 "
                    "{%0,%1,%2,%3}, {%4,%5,%6,%7}, {%8,%9}, {%0,%1,%2,%3};"
                    : "+f"(acc[nt][0]), "+f"(acc[nt][1]), "+f"(acc[nt][2]), "+f"(acc[nt][3])
                    : "r"(ah0), "r"(ah1), "r"(ah2), "r"(ah3),
                      "r"(__float_as_uint(bl0)), "r"(__float_as_uint(bl1)));
            }
        }

        // ---- store partials: zred[ks][l][b] ----
#pragma unroll
        for (int nt = 0; nt < 8; ++nt) {
            int l0 = mg * 16 + g;
            int n0 = nt * 8 + c * 2;
            *(float2*)&zred[(ks * 32 + l0) * 66 + n0]     = make_float2(acc[nt][0], acc[nt][1]);
            *(float2*)&zred[(ks * 32 + l0 + 8) * 66 + n0] = make_float2(acc[nt][2], acc[nt][3]);
        }
        __syncthreads();

        // ---- gate epilogue ----
        float hh0, hh1;
        {
            float vi0 = zi2.x, vi1 = zi2.y, vf0 = zf2.x, vf1 = zf2.y;
            float vg0 = zg2.x, vg1 = zg2.y, vo0 = zo2.x, vo1 = zo2.y;
#pragma unroll
            for (int k = 0; k < 4; ++k) {
                vi0 += zred[(k * 32 + q0)      * 66 + eb];
                vi1 += zred[(k * 32 + q0 + 1)  * 66 + eb];
                vf0 += zred[(k * 32 + 8 + q0)  * 66 + eb];
                vf1 += zred[(k * 32 + 9 + q0)  * 66 + eb];
                vg0 += zred[(k * 32 + 16 + q0) * 66 + eb];
                vg1 += zred[(k * 32 + 17 + q0) * 66 + eb];
                vo0 += zred[(k * 32 + 24 + q0) * 66 + eb];
                vo1 += zred[(k * 32 + 25 + q0) * 66 + eb];
            }
            float ig0 = fsigm(vi0), ig1 = fsigm(vi1);
            float fg0 = fsigm(vf0), fg1 = fsigm(vf1);
            float gg0 = ftanh(vg0), gg1 = ftanh(vg1);
            float og0 = fsigm(vo0), og1 = fsigm(vo1);
            cst0 = fg0 * cst0 + ig0 * gg0;
            cst1 = fg1 * cst1 + ig1 * gg1;
            hh0 = og0 * ftanh(cst0);
            hh1 = og1 * ftanh(cst1);

            __stcg(&hdst[(jb * 8 + q0) * 64 + eb],     hh0);
            __stcg(&hdst[(jb * 8 + q0 + 1) * 64 + eb], hh1);
        }

        bar_arrive(dir);

        size_t ho = ((size_t)eb * 1024 + t) * 1024 + dir * 512 + jb * 8 + q0;
        if (ROUND) {
            hout[ho]     = to_tf32(hh0);
            hout[ho + 1] = to_tf32(hh1);
        } else {
            hout[ho]     = hh0;
            hout[ho + 1] = hh1;
        }

        if (s + 1 < TSTEPS) {
            int tn = dir ? (TSTEPS - 2 - s) : (s + 1);
            const float* Zt = Z + ((size_t)tn * 64 + eb) * 2048 + jb * 8 + q0;
            zi2 = *(const float2*)(Zt + 0);
            zf2 = *(const float2*)(Zt + 512);
            zg2 = *(const float2*)(Zt + 1024);
            zo2 = *(const float2*)(Zt + 1536);
            bar_wait(dir, 64u * (unsigned)(s + 2));
        }
    }
}

__global__ void reset_bar_kernel() { g_bar2[0] = 0u; g_bar2[32] = 0u; }

// =====================================================================
extern "C" void kernel_launch(void* const* d_in, const int* in_sizes, int n_in,
                              void* d_out, int out_size)
{
    (void)in_sizes; (void)n_in; (void)out_size;
    const float* x   = (const float*)d_in[0];
    const float* W1f = (const float*)d_in[1];
    const float* U1f = (const float*)d_in[2];
    const float* b1f = (const float*)d_in[3];
    const float* W1b = (const float*)d_in[4];
    const float* U1b = (const float*)d_in[5];
    const float* b1b = (const float*)d_in[6];
    const float* W2f = (const float*)d_in[7];
    const float* U2f = (const float*)d_in[8];
    const float* b2f = (const float*)d_in[9];
    const float* W2b = (const float*)d_in[10];
    const float* U2b = (const float*)d_in[11];
    const float* b2b = (const float*)d_in[12];
    const float* Wd  = (const float*)d_in[13];
    const float* bd  = (const float*)d_in[14];
    float* out = (float*)d_out;

    float *Zf, *Zb, *h1, *h2, *xr;
    float *Wt1f, *Wt1b, *Wt2f, *Wt2b, *Wtd, *WtdLo;
    cudaGetSymbolAddress((void**)&Zf, g_Zf);
    cudaGetSymbolAddress((void**)&Zb, g_Zb);
    cudaGetSymbolAddress((void**)&h1, g_h1);
    cudaGetSymbolAddress((void**)&h2, g_h2);
    cudaGetSymbolAddress((void**)&xr, g_xr);
    cudaGetSymbolAddress((void**)&Wt1f, g_Wt1f);
    cudaGetSymbolAddress((void**)&Wt1b, g_Wt1b);
    cudaGetSymbolAddress((void**)&Wt2f, g_Wt2f);
    cudaGetSymbolAddress((void**)&Wt2b, g_Wt2b);
    cudaGetSymbolAddress((void**)&Wtd, g_Wtd);
    cudaGetSymbolAddress((void**)&WtdLo, g_WtdLo);

    const int GEMM_SMEM = 4 * ABUF * 4;
    cudaFuncSetAttribute(mma_gemm_kernel<0, 0>, cudaFuncAttributeMaxDynamicSharedMemorySize, GEMM_SMEM);
    cudaFuncSetAttribute(mma_gemm_kernel<0, 1>, cudaFuncAttributeMaxDynamicSharedMemorySize, GEMM_SMEM);
    cudaFuncSetAttribute(mma_gemm_kernel<1, 0>, cudaFuncAttributeMaxDynamicSharedMemorySize, GEMM_SMEM);
    cudaFuncSetAttribute(lstm_mma_kernel<0>, cudaFuncAttributeMaxDynamicSharedMemorySize, LSTM_SMEM);
    cudaFuncSetAttribute(lstm_mma_kernel<1>, cudaFuncAttributeMaxDynamicSharedMemorySize, LSTM_SMEM);

    dim3 blk(256);
    dim3 gZ(2048 / 128, 65536 / 128);
    dim3 gO(512 / 128, 65536 / 128);

    prep_all_kernel<<<dim3(2048, 6), 256>>>(x, xr, W1f, Wt1f, W1b, Wt1b,
                                            W2f, Wt2f, W2b, Wt2b, Wd, Wtd, WtdLo);
    mma_gemm_kernel<1, 0><<<gZ, blk, GEMM_SMEM>>>(xr, Wt1f, b1f, Zf, 512, 2048);
    mma_gemm_kernel<1, 0><<<gZ, blk, GEMM_SMEM>>>(xr, Wt1b, b1b, Zb, 512, 2048);
    reset_bar_kernel<<<1, 1>>>();

    // layer-1 recurrence
    lstm_mma_kernel<1><<<128, 256, LSTM_SMEM>>>(Zf, Zb, U1f, U1b, h1);

    // layer-2 input projections
    mma_gemm_kernel<1, 0><<<gZ, blk, GEMM_SMEM>>>(h1, Wt2f, b2f, Zf, 1024, 2048);
    mma_gemm_kernel<1, 0><<<gZ, blk, GEMM_SMEM>>>(h1, Wt2b, b2b, Zb, 1024, 2048);

    // layer-2 recurrence
    reset_bar_kernel<<<1, 1>>>();
    lstm_mma_kernel<0><<<128, 256, LSTM_SMEM>>>(Zf, Zb, U2f, U2b, h2);

    // dense head, 3-term split: out = (h1+h2)@Wd + bd
    add_split_kernel<<<(16777216 + 255) / 256, 256>>>(h1, h2, Zf, Zb, 16777216);
    mma_gemm_kernel<0, 0><<<gO, blk, GEMM_SMEM>>>(Zf, Wtd,   bd, out, 1024, 512);
    mma_gemm_kernel<0, 1><<<gO, blk, GEMM_SMEM>>>(Zb, Wtd,   bd, out, 1024, 512);
    mma_gemm_kernel<0, 1><<<gO, blk, GEMM_SMEM>>>(Zf, WtdLo, bd, out, 1024, 512);
}

// round 12
// speedup vs baseline: 2.4625x; 1.2004x over previous
#include <cuda_runtime.h>
#include <math.h>
#include <stdint.h>

#define TSTEPS 1024
#define BATCH  64
#define HID    512

// ---------------- scratch (static device allocations; no cudaMalloc) ----------------
__device__ float g_Zf[(size_t)TSTEPS * BATCH * 2048];   // Z fwd [t][b][4H]; later A_hi
__device__ float g_Zb[(size_t)TSTEPS * BATCH * 2048];   // Z bwd [t][b][4H]; later A_lo
__device__ float g_h1[(size_t)BATCH * TSTEPS * 1024];   // layer1 out [b][t][2H] (tf32)
__device__ float g_h2[(size_t)BATCH * TSTEPS * 1024];   // layer2 out [b][t][2H] (fp32)
__device__ float g_xr[(size_t)BATCH * TSTEPS * 512];    // tf32-rounded x
__device__ float g_hst[2][2][HID][BATCH];               // h state [dir][phase][col][b] (tf32)
__device__ unsigned int g_bar2[64];                     // per-dir barrier counters ([0],[32])

// transposed + tf32-rounded weights [N][K]
__device__ float g_Wt1f[2048 * 512];
__device__ float g_Wt1b[2048 * 512];
__device__ float g_Wt2f[2048 * 1024];
__device__ float g_Wt2b[2048 * 1024];
__device__ float g_Wtd [512 * 1024];
__device__ float g_WtdLo[512 * 1024];

__device__ __forceinline__ float to_tf32(float v) {
    float r; asm("cvt.rna.tf32.f32 %0, %1;" : "=f"(r) : "f"(v)); return r;
}
__device__ __forceinline__ uint32_t smem_u32(const void* p) {
    uint32_t a;
    asm("{ .reg .u64 t; cvta.to.shared.u64 t, %1; cvt.u32.u64 %0, t; }" : "=r"(a) : "l"(p));
    return a;
}
__device__ __forceinline__ float fsigm(float x) { return 1.f / (1.f + __expf(-x)); }
__device__ __forceinline__ float ftanh(float x) {
    float e = __expf(2.f * x);
    return 1.f - __fdividef(2.f, e + 1.f);
}
__device__ __forceinline__ void cp16(uint32_t dst, const void* src) {
    asm volatile("cp.async.cg.shared.global [%0], [%1], 16;" :: "r"(dst), "l"(src));
}

// =====================================================================
//  Fused prep kernel: blockIdx.y selects task.
// =====================================================================
__global__ void prep_all_kernel(
    const float* __restrict__ x,   float* __restrict__ xr,
    const float* __restrict__ W1f, float* __restrict__ Wt1f,
    const float* __restrict__ W1b, float* __restrict__ Wt1b,
    const float* __restrict__ W2f, float* __restrict__ Wt2f,
    const float* __restrict__ W2b, float* __restrict__ Wt2b,
    const float* __restrict__ Wd,  float* __restrict__ Wtd, float* __restrict__ WtdLo)
{
    const int task = blockIdx.y;
    if (task == 0) {
        const int n4 = 8388608;
        for (int i = blockIdx.x * 256 + threadIdx.x; i < n4; i += 2048 * 256) {
            float4 v = ((const float4*)x)[i];
            ((float4*)xr)[i] = make_float4(to_tf32(v.x), to_tf32(v.y),
                                           to_tf32(v.z), to_tf32(v.w));
        }
        return;
    }
    const float* W; float* Wt; float* Wlo = nullptr; int K, N;
    switch (task) {
        case 1: W = W1f; Wt = Wt1f; K = 512;  N = 2048; break;
        case 2: W = W1b; Wt = Wt1b; K = 512;  N = 2048; break;
        case 3: W = W2f; Wt = Wt2f; K = 1024; N = 2048; break;
        case 4: W = W2b; Wt = Wt2b; K = 1024; N = 2048; break;
        default: W = Wd; Wt = Wtd; Wlo = WtdLo; K = 1024; N = 512; break;
    }
    const int nkb = K / 32;
    const int total = nkb * (N / 32);
    const int bx = blockIdx.x;
    if (bx >= total) return;
    __shared__ float tile[32][33];
    const int kb = (bx % nkb) * 32, nb = (bx / nkb) * 32;
    const int tx = threadIdx.x & 31, ty = threadIdx.x >> 5;
#pragma unroll
    for (int i = ty; i < 32; i += 8)
        tile[i][tx] = W[(size_t)(kb + i) * N + nb + tx];
    __syncthreads();
#pragma unroll
    for (int i = ty; i < 32; i += 8) {
        float v = tile[tx][i];
        float hi = to_tf32(v);
        Wt[(size_t)(nb + i) * K + kb + tx] = hi;
        if (Wlo) Wlo[(size_t)(nb + i) * K + kb + tx] = to_tf32(v - hi);
    }
}

// A_hi = tf32(h1+h2), A_lo = tf32((h1+h2)-A_hi)
__global__ void add_split_kernel(const float* __restrict__ a, const float* __restrict__ b,
                                 float* __restrict__ ohi, float* __restrict__ olo, int n4)
{
    int i = blockIdx.x * blockDim.x + threadIdx.x;
    if (i < n4) {
        float4 va = ((const float4*)a)[i];
        float4 vb = ((const float4*)b)[i];
        float s0 = va.x + vb.x, s1 = va.y + vb.y, s2 = va.z + vb.z, s3 = va.w + vb.w;
        float h0 = to_tf32(s0), h1v = to_tf32(s1), h2v = to_tf32(s2), h3 = to_tf32(s3);
        ((float4*)ohi)[i] = make_float4(h0, h1v, h2v, h3);
        ((float4*)olo)[i] = make_float4(to_tf32(s0 - h0), to_tf32(s1 - h1v),
                                        to_tf32(s2 - h2v), to_tf32(s3 - h3));
    }
}

// =====================================================================
//  TF32 mma.sync GEMM (validated R4):  C = A @ Bt^T (+bias | +=)
// =====================================================================
#define ABUF 4608   // 128*36 floats per buffer

template <int SCATTER, int ACCUM>
__global__ void __launch_bounds__(256, 2)
mma_gemm_kernel(const float* __restrict__ A, const float* __restrict__ Bt,
                const float* __restrict__ bias, float* __restrict__ C, int K, int N)
{
    extern __shared__ float smf[];
    const int tid = threadIdx.x;
    const int wid = tid >> 5, lane = tid & 31;
    const int warp_m = wid & 1, warp_n = wid >> 1;
    const size_t rowBase = (size_t)blockIdx.y * 128;
    const size_t colBase = (size_t)blockIdx.x * 128;
    const uint32_t smbase = smem_u32(smf);
    const int NS = K >> 5;

    float acc[4][4][4];
#pragma unroll
    for (int mi = 0; mi < 4; ++mi)
#pragma unroll
        for (int ni = 0; ni < 4; ++ni)
#pragma unroll
            for (int r = 0; r < 4; ++r) acc[mi][ni][r] = 0.f;

    auto cp_tile = [&](int s, int p) {
        const int kt = s << 5;
#pragma unroll
        for (int i = 0; i < 4; ++i) {
            int idx = i * 256 + tid;
            int row = idx >> 3, f4 = idx & 7;
            uint32_t da = smbase + (uint32_t)((p * ABUF + row * 36 + f4 * 4) << 2);
            cp16(da, A + (rowBase + row) * K + kt + f4 * 4);
            uint32_t db = smbase + (uint32_t)(((2 * ABUF) + p * ABUF + row * 36 + f4 * 4) << 2);
            cp16(db, Bt + (colBase + row) * K + kt + f4 * 4);
        }
        asm volatile("cp.async.commit_group;");
    };

    cp_tile(0, 0);
    cp_tile(1, 1);

    const int g = lane >> 2, c = lane & 3;
    const int ar0 = warp_m * 64 + g;
    const int bn0 = warp_n * 32 + g;

    for (int s = 0; s < NS; ++s) {
        const int p = s & 1;
        if (s + 1 < NS) asm volatile("cp.async.wait_group 1;");
        else            asm volatile("cp.async.wait_group 0;");
        __syncthreads();

        const float* Ab = smf + p * ABUF;
        const float* Bb = smf + 2 * ABUF + p * ABUF;

#pragma unroll
        for (int k8 = 0; k8 < 4; ++k8) {
            const int kc = k8 * 8 + c;
            uint32_t a[4][4], b[4][2];
#pragma unroll
            for (int mi = 0; mi < 4; ++mi) {
                const float* base = Ab + (ar0 + mi * 16) * 36 + kc;
                a[mi][0] = __float_as_uint(base[0]);
                a[mi][1] = __float_as_uint(base[8 * 36]);
                a[mi][2] = __float_as_uint(base[4]);
                a[mi][3] = __float_as_uint(base[8 * 36 + 4]);
            }
#pragma unroll
            for (int ni = 0; ni < 4; ++ni) {
                const float* base = Bb + (bn0 + ni * 8) * 36 + kc;
                b[ni][0] = __float_as_uint(base[0]);
                b[ni][1] = __float_as_uint(base[4]);
            }
#pragma unroll
            for (int mi = 0; mi < 4; ++mi)
#pragma unroll
                for (int ni = 0; ni < 4; ++ni)
                    asm volatile(
                        "mma.sync.aligned.m16n8k8.row.col.f32.tf32.tf32.f32 "
                        "{%0,%1,%2,%3}, {%4,%5,%6,%7}, {%8,%9}, {%0,%1,%2,%3};"
                        : "+f"(acc[mi][ni][0]), "+f"(acc[mi][ni][1]),
                          "+f"(acc[mi][ni][2]), "+f"(acc[mi][ni][3])
                        : "r"(a[mi][0]), "r"(a[mi][1]), "r"(a[mi][2]), "r"(a[mi][3]),
                          "r"(b[ni][0]), "r"(b[ni][1]));
        }
        __syncthreads();
        if (s + 2 < NS) cp_tile(s + 2, p);
    }

    const int c2 = (lane & 3) * 2;
#pragma unroll
    for (int mi = 0; mi < 4; ++mi) {
        size_t r0 = rowBase + warp_m * 64 + mi * 16 + g;
        size_t r8 = r0 + 8;
        size_t off0, off8;
        if (SCATTER) {
            off0 = (((r0 & 1023) << 6) + (r0 >> 10)) * (size_t)N;
            off8 = (((r8 & 1023) << 6) + (r8 >> 10)) * (size_t)N;
        } else {
            off0 = r0 * (size_t)N;
            off8 = r8 * (size_t)N;
        }
#pragma unroll
        for (int ni = 0; ni < 4; ++ni) {
            size_t col = colBase + warp_n * 32 + ni * 8 + c2;
            float2 v0, v1;
            if (ACCUM) {
                float2 o0 = *(const float2*)&C[off0 + col];
                float2 o1 = *(const float2*)&C[off8 + col];
                v0 = make_float2(acc[mi][ni][0] + o0.x, acc[mi][ni][1] + o0.y);
                v1 = make_float2(acc[mi][ni][2] + o1.x, acc[mi][ni][3] + o1.y);
            } else {
                float2 bv = *(const float2*)&bias[col];
                v0 = make_float2(acc[mi][ni][0] + bv.x, acc[mi][ni][1] + bv.y);
                v1 = make_float2(acc[mi][ni][2] + bv.x, acc[mi][ni][3] + bv.y);
            }
            *(float2*)&C[off0 + col] = v0;
            *(float2*)&C[off8 + col] = v1;
        }
    }
}

// =====================================================================
//  Persistent bidirectional LSTM layer — tensor-core recurrence.
//  R12: SINGLE tf32 MMA per fragment. h state stored tf32-rounded at
//  epilogue, so the mainloop does zero conversions — staged bits feed
//  the MMA directly. (Revert point: re-add Uhi@Blo residual MMA.)
// =====================================================================
__device__ __forceinline__ void bar_arrive(int dir)
{
    __threadfence();
    __syncthreads();
    if (threadIdx.x == 0) atomicAdd(&g_bar2[dir * 32], 1u);
}
__device__ __forceinline__ void bar_wait(int dir, unsigned int target)
{
    if (threadIdx.x == 0)
        while (*(volatile unsigned int*)&g_bar2[dir * 32] < target) { }
    __syncthreads();
}

#define LSTM_SMEM ((36864 + 4 * 32 * 66) * 4)

template <int ROUND>
__global__ void __launch_bounds__(256, 1)
lstm_mma_kernel(const float* __restrict__ Zf, const float* __restrict__ Zb,
                const float* __restrict__ Uf, const float* __restrict__ Ub,
                float* __restrict__ hout)
{
    extern __shared__ float sm[];
    float* hs   = sm;           // [4 ks][128 k][72]  (pad-72)
    float* zred = sm + 36864;   // [4 ks][32 l][66]

    const int tid = threadIdx.x;
    const int w = tid >> 5, lane = tid & 31;
    const int g = lane >> 2, c = lane & 3;
    const int ks = w >> 1, mg = w & 1;
    const int dir = blockIdx.x >> 6;
    const int jb  = blockIdx.x & 63;
    const float* U = dir ? Ub : Uf;
    const float* Z = dir ? Zb : Zf;
    float* hst0 = &g_hst[dir][0][0][0];
    float* hst1 = &g_hst[dir][1][0][0];

    // ---- one-time: U A-fragments (tf32-rounded), registers ----
    float uhi[16][4];
    {
        const int l0 = mg * 16 + g, l1 = l0 + 8;
        const int gc0 = (l0 >> 3) * 512 + jb * 8 + (l0 & 7);
        const int gc1 = (l1 >> 3) * 512 + jb * 8 + (l1 & 7);
#pragma unroll
        for (int kk = 0; kk < 16; ++kk) {
            int k = ks * 128 + kk * 8;
            uhi[kk][0] = to_tf32(U[(size_t)(k + c) * 2048 + gc0]);
            uhi[kk][1] = to_tf32(U[(size_t)(k + c) * 2048 + gc1]);
            uhi[kk][2] = to_tf32(U[(size_t)(k + c + 4) * 2048 + gc0]);
            uhi[kk][3] = to_tf32(U[(size_t)(k + c + 4) * 2048 + gc1]);
        }
    }

    // zero own cols of phase-0 state
    for (int i = tid; i < 512; i += 256) hst0[jb * 8 * 64 + i] = 0.f;
    bar_arrive(dir);
    bar_wait(dir, 64u);

    const int eb = tid >> 2;
    const int q0 = (tid & 3) * 2;
    float cst0 = 0.f, cst1 = 0.f;
    const int pt = tid & 63;
    float* hsP = hs + ks * 9216;
    const uint32_t hsPb = smem_u32(hsP);

    // prologue Z prefetch for s=0
    float2 zi2, zf2, zg2, zo2;
    {
        int t0 = dir ? (TSTEPS - 1) : 0;
        const float* Zt = Z + ((size_t)t0 * 64 + eb) * 2048 + jb * 8 + q0;
        zi2 = *(const float2*)(Zt + 0);
        zf2 = *(const float2*)(Zt + 512);
        zg2 = *(const float2*)(Zt + 1024);
        zo2 = *(const float2*)(Zt + 1536);
    }

    for (int s = 0; s < TSTEPS; ++s) {
        const int t = dir ? (TSTEPS - 1 - s) : s;
        const float* hsrc = (s & 1) ? hst1 : hst0;
        float* hdst = (s & 1) ? hst0 : hst1;

        // ---- stage pair's K-slice via cp.async: [col][b] -> smem [k][72] ----
        {
            const float4* src = (const float4*)(hsrc + ks * 8192);
#pragma unroll
            for (int i = 0; i < 32; ++i) {
                int idx = i * 64 + pt;
                int kl = idx >> 4, q4 = idx & 15;
                cp16(hsPb + (uint32_t)((kl * 72 + q4 * 4) << 2), src + idx);
            }
            asm volatile("cp.async.commit_group;");
            asm volatile("cp.async.wait_group 0;");
        }
        asm volatile("bar.sync %0, %1;" :: "r"(1 + ks), "r"(64) : "memory");

        // ---- MMA: z[l=mg*16..+16][b=0..63] over k in [ks*128,+128) ----
        // h is already tf32 in smem: feed bits straight to the MMA.
        float acc[8][4];
#pragma unroll
        for (int nt = 0; nt < 8; ++nt)
#pragma unroll
            for (int r = 0; r < 4; ++r) acc[nt][r] = 0.f;

#pragma unroll
        for (int kk = 0; kk < 16; ++kk) {
            uint32_t ah0 = __float_as_uint(uhi[kk][0]), ah1 = __float_as_uint(uhi[kk][1]);
            uint32_t ah2 = __float_as_uint(uhi[kk][2]), ah3 = __float_as_uint(uhi[kk][3]);
            const uint32_t* rowA = (const uint32_t*)(hsP + (kk * 8 + c) * 72);
            const uint32_t* rowB = rowA + 4 * 72;
#pragma unroll
            for (int nt = 0; nt < 8; ++nt) {
                uint32_t b0 = rowA[nt * 8 + g];
                uint32_t b1 = rowB[nt * 8 + g];
                asm volatile(
                    "mma.sync.aligned.m16n8k8.row.col.f32.tf32.tf32.f32 "
                    "{%0,%1,%2,%3}, {%4,%5,%6,%7}, {%8,%9}, {%0,%1,%2,%3};"
                    : "+f"(acc[nt][0]), "+f"(acc[nt][1]), "+f"(acc[nt][2]), "+f"(acc[nt][3])
                    : "r"(ah0), "r"(ah1), "r"(ah2), "r"(ah3),
                      "r"(b0), "r"(b1));
            }
        }

        // ---- store partials: zred[ks][l][b] ----
#pragma unroll
        for (int nt = 0; nt < 8; ++nt) {
            int l0 = mg * 16 + g;
            int n0 = nt * 8 + c * 2;
            *(float2*)&zred[(ks * 32 + l0) * 66 + n0]     = make_float2(acc[nt][0], acc[nt][1]);
            *(float2*)&zred[(ks * 32 + l0 + 8) * 66 + n0] = make_float2(acc[nt][2], acc[nt][3]);
        }
        __syncthreads();

        // ---- gate epilogue ----
        float hh0, hh1;
        {
            float vi0 = zi2.x, vi1 = zi2.y, vf0 = zf2.x, vf1 = zf2.y;
            float vg0 = zg2.x, vg1 = zg2.y, vo0 = zo2.x, vo1 = zo2.y;
#pragma unroll
            for (int k = 0; k < 4; ++k) {
                vi0 += zred[(k * 32 + q0)      * 66 + eb];
                vi1 += zred[(k * 32 + q0 + 1)  * 66 + eb];
                vf0 += zred[(k * 32 + 8 + q0)  * 66 + eb];
                vf1 += zred[(k * 32 + 9 + q0)  * 66 + eb];
                vg0 += zred[(k * 32 + 16 + q0) * 66 + eb];
                vg1 += zred[(k * 32 + 17 + q0) * 66 + eb];
                vo0 += zred[(k * 32 + 24 + q0) * 66 + eb];
                vo1 += zred[(k * 32 + 25 + q0) * 66 + eb];
            }
            float ig0 = fsigm(vi0), ig1 = fsigm(vi1);
            float fg0 = fsigm(vf0), fg1 = fsigm(vf1);
            float gg0 = ftanh(vg0), gg1 = ftanh(vg1);
            float og0 = fsigm(vo0), og1 = fsigm(vo1);
            cst0 = fg0 * cst0 + ig0 * gg0;
            cst1 = fg1 * cst1 + ig1 * gg1;
            hh0 = og0 * ftanh(cst0);
            hh1 = og1 * ftanh(cst1);

            // state stored tf32-rounded (mainloop feeds bits to MMA directly)
            __stcg(&hdst[(jb * 8 + q0) * 64 + eb],     to_tf32(hh0));
            __stcg(&hdst[(jb * 8 + q0 + 1) * 64 + eb], to_tf32(hh1));
        }

        bar_arrive(dir);

        size_t ho = ((size_t)eb * 1024 + t) * 1024 + dir * 512 + jb * 8 + q0;
        if (ROUND) {
            hout[ho]     = to_tf32(hh0);
            hout[ho + 1] = to_tf32(hh1);
        } else {
            hout[ho]     = hh0;
            hout[ho + 1] = hh1;
        }

        if (s + 1 < TSTEPS) {
            int tn = dir ? (TSTEPS - 2 - s) : (s + 1);
            const float* Zt = Z + ((size_t)tn * 64 + eb) * 2048 + jb * 8 + q0;
            zi2 = *(const float2*)(Zt + 0);
            zf2 = *(const float2*)(Zt + 512);
            zg2 = *(const float2*)(Zt + 1024);
            zo2 = *(const float2*)(Zt + 1536);
            bar_wait(dir, 64u * (unsigned)(s + 2));
        }
    }
}

__global__ void reset_bar_kernel() { g_bar2[0] = 0u; g_bar2[32] = 0u; }

// =====================================================================
extern "C" void kernel_launch(void* const* d_in, const int* in_sizes, int n_in,
                              void* d_out, int out_size)
{
    (void)in_sizes; (void)n_in; (void)out_size;
    const float* x   = (const float*)d_in[0];
    const float* W1f = (const float*)d_in[1];
    const float* U1f = (const float*)d_in[2];
    const float* b1f = (const float*)d_in[3];
    const float* W1b = (const float*)d_in[4];
    const float* U1b = (const float*)d_in[5];
    const float* b1b = (const float*)d_in[6];
    const float* W2f = (const float*)d_in[7];
    const float* U2f = (const float*)d_in[8];
    const float* b2f = (const float*)d_in[9];
    const float* W2b = (const float*)d_in[10];
    const float* U2b = (const float*)d_in[11];
    const float* b2b = (const float*)d_in[12];
    const float* Wd  = (const float*)d_in[13];
    const float* bd  = (const float*)d_in[14];
    float* out = (float*)d_out;

    float *Zf, *Zb, *h1, *h2, *xr;
    float *Wt1f, *Wt1b, *Wt2f, *Wt2b, *Wtd, *WtdLo;
    cudaGetSymbolAddress((void**)&Zf, g_Zf);
    cudaGetSymbolAddress((void**)&Zb, g_Zb);
    cudaGetSymbolAddress((void**)&h1, g_h1);
    cudaGetSymbolAddress((void**)&h2, g_h2);
    cudaGetSymbolAddress((void**)&xr, g_xr);
    cudaGetSymbolAddress((void**)&Wt1f, g_Wt1f);
    cudaGetSymbolAddress((void**)&Wt1b, g_Wt1b);
    cudaGetSymbolAddress((void**)&Wt2f, g_Wt2f);
    cudaGetSymbolAddress((void**)&Wt2b, g_Wt2b);
    cudaGetSymbolAddress((void**)&Wtd, g_Wtd);
    cudaGetSymbolAddress((void**)&WtdLo, g_WtdLo);

    const int GEMM_SMEM = 4 * ABUF * 4;
    cudaFuncSetAttribute(mma_gemm_kernel<0, 0>, cudaFuncAttributeMaxDynamicSharedMemorySize, GEMM_SMEM);
    cudaFuncSetAttribute(mma_gemm_kernel<0, 1>, cudaFuncAttributeMaxDynamicSharedMemorySize, GEMM_SMEM);
    cudaFuncSetAttribute(mma_gemm_kernel<1, 0>, cudaFuncAttributeMaxDynamicSharedMemorySize, GEMM_SMEM);
    cudaFuncSetAttribute(lstm_mma_kernel<0>, cudaFuncAttributeMaxDynamicSharedMemorySize, LSTM_SMEM);
    cudaFuncSetAttribute(lstm_mma_kernel<1>, cudaFuncAttributeMaxDynamicSharedMemorySize, LSTM_SMEM);

    dim3 blk(256);
    dim3 gZ(2048 / 128, 65536 / 128);
    dim3 gO(512 / 128, 65536 / 128);

    prep_all_kernel<<<dim3(2048, 6), 256>>>(x, xr, W1f, Wt1f, W1b, Wt1b,
                                            W2f, Wt2f, W2b, Wt2b, Wd, Wtd, WtdLo);
    mma_gemm_kernel<1, 0><<<gZ, blk, GEMM_SMEM>>>(xr, Wt1f, b1f, Zf, 512, 2048);
    mma_gemm_kernel<1, 0><<<gZ, blk, GEMM_SMEM>>>(xr, Wt1b, b1b, Zb, 512, 2048);
    reset_bar_kernel<<<1, 1>>>();

    // layer-1 recurrence
    lstm_mma_kernel<1><<<128, 256, LSTM_SMEM>>>(Zf, Zb, U1f, U1b, h1);

    // layer-2 input projections
    mma_gemm_kernel<1, 0><<<gZ, blk, GEMM_SMEM>>>(h1, Wt2f, b2f, Zf, 1024, 2048);
    mma_gemm_kernel<1, 0><<<gZ, blk, GEMM_SMEM>>>(h1, Wt2b, b2b, Zb, 1024, 2048);

    // layer-2 recurrence
    reset_bar_kernel<<<1, 1>>>();
    lstm_mma_kernel<0><<<128, 256, LSTM_SMEM>>>(Zf, Zb, U2f, U2b, h2);

    // dense head, 3-term split: out = (h1+h2)@Wd + bd
    add_split_kernel<<<(16777216 + 255) / 256, 256>>>(h1, h2, Zf, Zb, 16777216);
    mma_gemm_kernel<0, 0><<<gO, blk, GEMM_SMEM>>>(Zf, Wtd,   bd, out, 1024, 512);
    mma_gemm_kernel<0, 1><<<gO, blk, GEMM_SMEM>>>(Zb, Wtd,   bd, out, 1024, 512);
    mma_gemm_kernel<0, 1><<<gO, blk, GEMM_SMEM>>>(Zf, WtdLo, bd, out, 1024, 512);
}